// round 5
// baseline (speedup 1.0000x reference)
#include <cuda_runtime.h>
#include <math.h>

// ---------------- problem constants ----------------
#define BATCH    2
#define SEQ      1024
#define DMODEL   1024
#define DINNER   2048
#define DSTATE   16
#define NTOK     (BATCH * SEQ)          // 2048
#define XW       (DINNER + 2 * DSTATE)  // 2080
#define NSEG     32
#define GSEG     32                     // SEQ / NSEG

// ---------------- scratch ----------------
__device__ float g_xn [NTOK * DMODEL];
__device__ float g_xr [NTOK * 2 * DINNER];
__device__ float g_xs [NTOK * DINNER];
__device__ float g_ssm[NTOK * XW];
__device__ float g_dt [NTOK * DINNER];
__device__ float g_yz [NTOK * DINNER];
__device__ float g_P  [BATCH * NSEG * DSTATE * DINNER];
__device__ float g_Q  [BATCH * NSEG * DSTATE * DINNER];
__device__ float g_H  [BATCH * NSEG * DSTATE * DINNER];

// ---------------- helpers ----------------
__device__ __forceinline__ void upk2(unsigned long long v, float& lo, float& hi) {
    asm("mov.b64 {%0, %1}, %2;" : "=f"(lo), "=f"(hi) : "l"(v));
}
__device__ __forceinline__ void cp_async16(void* sptr, const void* gptr) {
    unsigned int saddr = (unsigned int)__cvta_generic_to_shared(sptr);
    asm volatile("cp.async.cg.shared.global [%0], [%1], 16;\n"
                 :: "r"(saddr), "l"(gptr));
}
__device__ __forceinline__ void cp_commit() {
    asm volatile("cp.async.commit_group;\n");
}
__device__ __forceinline__ void cp_wait1() {
    asm volatile("cp.async.wait_group 1;\n" ::: "memory");
}

// ---------------- RMSNorm ----------------
__global__ void rmsnorm_kernel(const float* __restrict__ x,
                               const float* __restrict__ w,
                               float* __restrict__ xn) {
    const int t   = blockIdx.x;
    const int tid = threadIdx.x;
    const float4 v = reinterpret_cast<const float4*>(x + t * DMODEL)[tid];
    float s = v.x * v.x + v.y * v.y + v.z * v.z + v.w * v.w;
    #pragma unroll
    for (int o = 16; o; o >>= 1) s += __shfl_xor_sync(0xffffffffu, s, o);
    __shared__ float red[8];
    __shared__ float sscale;
    if ((tid & 31) == 0) red[tid >> 5] = s;
    __syncthreads();
    if (tid == 0) {
        float tot = 0.f;
        #pragma unroll
        for (int i = 0; i < 8; ++i) tot += red[i];
        sscale = rsqrtf(tot * (1.0f / DMODEL) + 1e-5f);
    }
    __syncthreads();
    const float sc = sscale;
    const float4 wv = reinterpret_cast<const float4*>(w)[tid];
    float4 o;
    o.x = v.x * sc * wv.x;  o.y = v.y * sc * wv.y;
    o.z = v.z * sc * wv.z;  o.w = v.w * sc * wv.w;
    reinterpret_cast<float4*>(xn + t * DMODEL)[tid] = o;
}

// ---------------- depthwise causal conv (d_conv=4) + SiLU ----------------
__global__ void conv_silu_kernel(const float* __restrict__ xr,
                                 const float* __restrict__ cw,
                                 const float* __restrict__ cb,
                                 float* __restrict__ xs) {
    const int idx = blockIdx.x * blockDim.x + threadIdx.x;
    const int d   = idx & (DINNER - 1);
    const int tok = idx >> 11;
    const int l   = tok & (SEQ - 1);
    float acc = cb[d];
    #pragma unroll
    for (int j = 0; j < 4; ++j) {
        const int ls = l - 3 + j;
        if (ls >= 0)
            acc = fmaf(cw[d * 4 + j], xr[(tok + j - 3) * (2 * DINNER) + d], acc);
    }
    xs[idx] = acc / (1.f + __expf(-acc));
}

// ---------------- tiled fp32 GEMM ----------------
// A stored in smem PRE-DUPLICATED as float2 (a,a): the f32x2 broadcast operand
// comes straight out of LDS.128 -> zero pair-building MOVs in the hot loop.
#define BM 128
#define BN 128
#define BK 16
#define SPAD 4
#define APAD 2          // float2 units of padding per As2 row

#define AS2_BYTES (2 * BK * (BM + APAD) * 8)              // 33280
#define BS_BYTES  (3 * BK * (BN + SPAD) * 4)              // 25344
#define SMEM_GEMM (AS2_BYTES + BS_BYTES)                  // 58624

#define ACT_NONE     0
#define ACT_SOFTPLUS 1
#define ACT_RESADD   2

template <int ACT>
__global__ __launch_bounds__(256, 2)
void gemm_kernel(const float* __restrict__ A, const float* __restrict__ B,
                 float* __restrict__ D, const float* __restrict__ Res,
                 int N, int K, int lda, int ldb, int ldd, int ldr) {
    extern __shared__ unsigned char smraw[];
    float2 (*As2)[BK][BM + APAD] =
        reinterpret_cast<float2 (*)[BK][BM + APAD]>(smraw);
    float (*Bs)[BK][BN + SPAD] =
        reinterpret_cast<float (*)[BK][BN + SPAD]>(smraw + AS2_BYTES);

    const int tid = threadIdx.x;
    const int tx  = tid & 15;
    const int ty  = tid >> 4;
    const int m0  = blockIdx.y * BM;
    const int n0  = blockIdx.x * BN;

    const int arow = tid >> 2;          // 0..63
    const int acol = (tid & 3) << 2;    // 0,4,8,12
    const int brow = tid >> 5;          // 0..7
    const int bcol = (tid & 31) << 2;   // 0..124
    const bool bok = (n0 + bcol) < N;

    // OOB B slots: zero once; never overwritten by cp.async afterwards.
    if (!bok) {
        #pragma unroll
        for (int st = 0; st < 3; ++st) {
            *reinterpret_cast<float4*>(&Bs[st][brow][bcol])     = make_float4(0,0,0,0);
            *reinterpret_cast<float4*>(&Bs[st][brow + 8][bcol]) = make_float4(0,0,0,0);
        }
    }

    const float* Ag = A + m0 * lda;
    const int T = K / BK;

#define STASH_A(ST, V0, V1) do {                                          \
        As2[ST][acol + 0][arow] = make_float2((V0).x, (V0).x);            \
        As2[ST][acol + 1][arow] = make_float2((V0).y, (V0).y);            \
        As2[ST][acol + 2][arow] = make_float2((V0).z, (V0).z);            \
        As2[ST][acol + 3][arow] = make_float2((V0).w, (V0).w);            \
        As2[ST][acol + 0][arow + 64] = make_float2((V1).x, (V1).x);       \
        As2[ST][acol + 1][arow + 64] = make_float2((V1).y, (V1).y);       \
        As2[ST][acol + 2][arow + 64] = make_float2((V1).z, (V1).z);       \
        As2[ST][acol + 3][arow + 64] = make_float2((V1).w, (V1).w);       \
    } while (0)

    // ---- prolog: A tile0 -> smem, A tile1 -> regs, B tiles 0,1 via cp.async
    float4 av0 = *reinterpret_cast<const float4*>(&Ag[arow * lda + acol]);
    float4 av1 = *reinterpret_cast<const float4*>(&Ag[(arow + 64) * lda + acol]);
    STASH_A(0, av0, av1);
    av0 = *reinterpret_cast<const float4*>(&Ag[arow * lda + BK + acol]);
    av1 = *reinterpret_cast<const float4*>(&Ag[(arow + 64) * lda + BK + acol]);

    if (bok) {
        cp_async16(&Bs[0][brow][bcol],     &B[brow * ldb + n0 + bcol]);
        cp_async16(&Bs[0][brow + 8][bcol], &B[(brow + 8) * ldb + n0 + bcol]);
    }
    cp_commit();
    if (bok) {
        cp_async16(&Bs[1][brow][bcol],     &B[(BK + brow) * ldb + n0 + bcol]);
        cp_async16(&Bs[1][brow + 8][bcol], &B[(BK + brow + 8) * ldb + n0 + bcol]);
    }
    cp_commit();

    unsigned long long acc[8][4];
    #pragma unroll
    for (int i = 0; i < 8; ++i)
        #pragma unroll
        for (int j = 0; j < 4; ++j) acc[i][j] = 0ULL;

    for (int i = 0; i < T; ++i) {
        cp_wait1();          // B tile i resident
        __syncthreads();     // everyone done with previous buffers; tile-i visible

        if (i + 1 < T) {     // stash A tile i+1 (held in regs)
            const int ab = (i + 1) & 1;
            STASH_A(ab, av0, av1);
        }
        if (i + 2 < T) {     // start fetching tile i+2
            av0 = *reinterpret_cast<const float4*>(&Ag[arow * lda + (i + 2) * BK + acol]);
            av1 = *reinterpret_cast<const float4*>(&Ag[(arow + 64) * lda + (i + 2) * BK + acol]);
            if (bok) {
                const int bsn = (i + 2) % 3;
                cp_async16(&Bs[bsn][brow][bcol],
                           &B[((i + 2) * BK + brow) * ldb + n0 + bcol]);
                cp_async16(&Bs[bsn][brow + 8][bcol],
                           &B[((i + 2) * BK + brow + 8) * ldb + n0 + bcol]);
            }
        }
        cp_commit();

        const int ab = i & 1, bs = i % 3;
        #pragma unroll
        for (int k = 0; k < BK; ++k) {
            // A broadcast pairs: 4 x LDS.128 -> 8 ready f32x2 operands
            const ulonglong2 t0 = *reinterpret_cast<const ulonglong2*>(&As2[ab][k][ty * 8 + 0]);
            const ulonglong2 t1 = *reinterpret_cast<const ulonglong2*>(&As2[ab][k][ty * 8 + 2]);
            const ulonglong2 t2 = *reinterpret_cast<const ulonglong2*>(&As2[ab][k][ty * 8 + 4]);
            const ulonglong2 t3 = *reinterpret_cast<const ulonglong2*>(&As2[ab][k][ty * 8 + 6]);
            const unsigned long long a2[8] =
                {t0.x, t0.y, t1.x, t1.y, t2.x, t2.y, t3.x, t3.y};
            const ulonglong2 bA = *reinterpret_cast<const ulonglong2*>(&Bs[bs][k][tx * 4]);
            const ulonglong2 bB = *reinterpret_cast<const ulonglong2*>(&Bs[bs][k][tx * 4 + 64]);
            const unsigned long long b2[4] = {bA.x, bA.y, bB.x, bB.y};
            #pragma unroll
            for (int r = 0; r < 8; ++r) {
                #pragma unroll
                for (int j = 0; j < 4; ++j)
                    asm("fma.rn.f32x2 %0, %1, %2, %0;"
                        : "+l"(acc[r][j]) : "l"(a2[r]), "l"(b2[j]));
            }
        }
    }

    // ---- epilogue
    #pragma unroll
    for (int i = 0; i < 8; ++i) {
        const int row = m0 + ty * 8 + i;
        float c[8];
        upk2(acc[i][0], c[0], c[1]);  upk2(acc[i][1], c[2], c[3]);
        upk2(acc[i][2], c[4], c[5]);  upk2(acc[i][3], c[6], c[7]);
        const int c0 = n0 + tx * 4;
        const int c1 = n0 + 64 + tx * 4;
        if (ACT == ACT_SOFTPLUS) {
            #pragma unroll
            for (int j = 0; j < 8; ++j)
                c[j] = fmaxf(c[j], 0.f) + log1pf(__expf(-fabsf(c[j])));
        }
        if (ACT == ACT_RESADD) {
            if (c0 < N) {
                const float4 r = *reinterpret_cast<const float4*>(&Res[row * ldr + c0]);
                c[0] += r.x; c[1] += r.y; c[2] += r.z; c[3] += r.w;
            }
            if (c1 < N) {
                const float4 r = *reinterpret_cast<const float4*>(&Res[row * ldr + c1]);
                c[4] += r.x; c[5] += r.y; c[6] += r.z; c[7] += r.w;
            }
        }
        if (c0 < N)
            *reinterpret_cast<float4*>(&D[row * ldd + c0]) =
                make_float4(c[0], c[1], c[2], c[3]);
        if (c1 < N)
            *reinterpret_cast<float4*>(&D[row * ldd + c1]) =
                make_float4(c[4], c[5], c[6], c[7]);
    }
#undef STASH_A
}

// ---------------- chunked parallel selective scan ----------------
__global__ __launch_bounds__(256)
void scan_p1(const float* __restrict__ dt, const float* __restrict__ xs,
             const float* __restrict__ ssm, const float* __restrict__ A_log,
             float* __restrict__ P, float* __restrict__ Q) {
    __shared__ float Bsh[GSEG][DSTATE];
    const int b = blockIdx.z, s = blockIdx.y;
    const int d = blockIdx.x * 256 + threadIdx.x;
    const int tok0 = b * SEQ + s * GSEG;

    for (int v = threadIdx.x; v < GSEG * DSTATE; v += 256) {
        const int l = v >> 4, n = v & 15;
        Bsh[l][n] = ssm[(tok0 + l) * XW + DINNER + n];
    }
    __syncthreads();

    float Ac[DSTATE];
    #pragma unroll
    for (int q = 0; q < 4; ++q) {
        const float4 v = reinterpret_cast<const float4*>(&A_log[d * DSTATE])[q];
        Ac[4 * q + 0] = -__expf(v.x);  Ac[4 * q + 1] = -__expf(v.y);
        Ac[4 * q + 2] = -__expf(v.z);  Ac[4 * q + 3] = -__expf(v.w);
    }

    float h[DSTATE];
    #pragma unroll
    for (int n = 0; n < DSTATE; ++n) h[n] = 0.f;
    float sdt = 0.f;

    for (int l = 0; l < GSEG; ++l) {
        const float dtv = dt[(tok0 + l) * DINNER + d];
        const float xv  = xs[(tok0 + l) * DINNER + d];
        sdt += dtv;
        const float dtx = dtv * xv;
        #pragma unroll
        for (int n = 0; n < DSTATE; ++n)
            h[n] = fmaf(__expf(Ac[n] * dtv), h[n], dtx * Bsh[l][n]);
    }

    const int base = ((b * NSEG + s) * DSTATE) * DINNER + d;
    #pragma unroll
    for (int n = 0; n < DSTATE; ++n) {
        P[base + n * DINNER] = __expf(Ac[n] * sdt);
        Q[base + n * DINNER] = h[n];
    }
}

__global__ void scan_combine(const float* __restrict__ P,
                             const float* __restrict__ Q,
                             float* __restrict__ H) {
    const int t = blockIdx.x * 256 + threadIdx.x;   // 65536
    const int d = t & (DINNER - 1);
    const int n = (t >> 11) & 15;
    const int b = t >> 15;
    float h = 0.f;
    for (int s = 0; s < NSEG; ++s) {
        const int off = ((b * NSEG + s) * DSTATE + n) * DINNER + d;
        H[off] = h;
        h = fmaf(P[off], h, Q[off]);
    }
}

__global__ __launch_bounds__(256)
void scan_p2(const float* __restrict__ dt, const float* __restrict__ xs,
             const float* __restrict__ ssm, const float* __restrict__ xr,
             const float* __restrict__ A_log, const float* __restrict__ H,
             float* __restrict__ yz) {
    __shared__ float Bsh[GSEG][DSTATE];
    __shared__ float Csh[GSEG][DSTATE];
    const int b = blockIdx.z, s = blockIdx.y;
    const int d = blockIdx.x * 256 + threadIdx.x;
    const int tok0 = b * SEQ + s * GSEG;

    for (int v = threadIdx.x; v < GSEG * DSTATE * 2; v += 256) {
        const int l = v >> 5, j = v & 31;
        const float val = ssm[(tok0 + l) * XW + DINNER + j];
        if (j < DSTATE) Bsh[l][j] = val;
        else            Csh[l][j - DSTATE] = val;
    }
    __syncthreads();

    float Ac[DSTATE];
    #pragma unroll
    for (int q = 0; q < 4; ++q) {
        const float4 v = reinterpret_cast<const float4*>(&A_log[d * DSTATE])[q];
        Ac[4 * q + 0] = -__expf(v.x);  Ac[4 * q + 1] = -__expf(v.y);
        Ac[4 * q + 2] = -__expf(v.z);  Ac[4 * q + 3] = -__expf(v.w);
    }

    const int base = ((b * NSEG + s) * DSTATE) * DINNER + d;
    float h[DSTATE];
    #pragma unroll
    for (int n = 0; n < DSTATE; ++n) h[n] = H[base + n * DINNER];

    for (int l = 0; l < GSEG; ++l) {
        const float dtv = dt[(tok0 + l) * DINNER + d];
        const float xv  = xs[(tok0 + l) * DINNER + d];
        const float dtx = dtv * xv;
        float y = 0.f;
        #pragma unroll
        for (int n = 0; n < DSTATE; ++n) {
            h[n] = fmaf(__expf(Ac[n] * dtv), h[n], dtx * Bsh[l][n]);
            y = fmaf(h[n], Csh[l][n], y);
        }
        const float r = xr[(tok0 + l) * (2 * DINNER) + DINNER + d];
        yz[(tok0 + l) * DINNER + d] = y * (r / (1.f + __expf(-r)));
    }
}

// ---------------- launch ----------------
extern "C" void kernel_launch(void* const* d_in, const int* in_sizes, int n_in,
                              void* d_out, int out_size) {
    const float* x      = (const float*)d_in[0];
    const float* rms_w  = (const float*)d_in[1];
    const float* W_in   = (const float*)d_in[2];
    const float* conv_w = (const float*)d_in[3];
    const float* conv_b = (const float*)d_in[4];
    const float* W_x    = (const float*)d_in[5];
    const float* W_dt   = (const float*)d_in[6];
    const float* A_log  = (const float*)d_in[7];
    const float* W_out  = (const float*)d_in[8];
    float* out = (float*)d_out;

    float *xn, *xr, *xs, *ssm, *dtb, *yz, *P, *Q, *H;
    cudaGetSymbolAddress((void**)&xn,  g_xn);
    cudaGetSymbolAddress((void**)&xr,  g_xr);
    cudaGetSymbolAddress((void**)&xs,  g_xs);
    cudaGetSymbolAddress((void**)&ssm, g_ssm);
    cudaGetSymbolAddress((void**)&dtb, g_dt);
    cudaGetSymbolAddress((void**)&yz,  g_yz);
    cudaGetSymbolAddress((void**)&P,   g_P);
    cudaGetSymbolAddress((void**)&Q,   g_Q);
    cudaGetSymbolAddress((void**)&H,   g_H);

    // opt-in to >48KB dynamic smem (idempotent host calls; not captured ops)
    static bool attr_done = false;
    if (!attr_done) {
        cudaFuncSetAttribute(gemm_kernel<ACT_NONE>,
            cudaFuncAttributeMaxDynamicSharedMemorySize, SMEM_GEMM);
        cudaFuncSetAttribute(gemm_kernel<ACT_SOFTPLUS>,
            cudaFuncAttributeMaxDynamicSharedMemorySize, SMEM_GEMM);
        cudaFuncSetAttribute(gemm_kernel<ACT_RESADD>,
            cudaFuncAttributeMaxDynamicSharedMemorySize, SMEM_GEMM);
        attr_done = true;
    }

    // 1. RMSNorm
    rmsnorm_kernel<<<NTOK, 256>>>(x, rms_w, xn);

    // 2. xr = xn @ W_in          [2048,4096]
    gemm_kernel<ACT_NONE><<<dim3(4096 / BN, NTOK / BM), 256, SMEM_GEMM>>>(
        xn, W_in, xr, nullptr, 4096, DMODEL, DMODEL, 4096, 4096, 0);

    // 3. depthwise conv + silu   [2048,2048]
    conv_silu_kernel<<<(NTOK * DINNER) / 256, 256>>>(xr, conv_w, conv_b, xs);

    // 4. x_ssm = xs @ W_x        [2048,2080]
    gemm_kernel<ACT_NONE><<<dim3((XW + BN - 1) / BN, NTOK / BM), 256, SMEM_GEMM>>>(
        xs, W_x, ssm, nullptr, XW, DINNER, DINNER, XW, XW, 0);

    // 5. dt = softplus(x_ssm[:, :2048] @ W_dt)
    gemm_kernel<ACT_SOFTPLUS><<<dim3(DINNER / BN, NTOK / BM), 256, SMEM_GEMM>>>(
        ssm, W_dt, dtb, nullptr, DINNER, DINNER, XW, DINNER, DINNER, 0);

    // 6. chunked parallel scan
    scan_p1<<<dim3(DINNER / 256, NSEG, BATCH), 256>>>(dtb, xs, ssm, A_log, P, Q);
    scan_combine<<<(BATCH * DSTATE * DINNER) / 256, 256>>>(P, Q, H);
    scan_p2<<<dim3(DINNER / 256, NSEG, BATCH), 256>>>(dtb, xs, ssm, xr, A_log, H, yz);

    // 7. out = x + yz @ W_out
    gemm_kernel<ACT_RESADD><<<dim3(DMODEL / BN, NTOK / BM), 256, SMEM_GEMM>>>(
        yz, W_out, out, x, DMODEL, DINNER, DINNER, DMODEL, DMODEL, DMODEL);
}

// round 7
// speedup vs baseline: 1.9377x; 1.9377x over previous
#include <cuda_runtime.h>
#include <cuda_bf16.h>
#include <math.h>
#include <stdint.h>

// ---------------- problem constants ----------------
#define BATCH    2
#define SEQ      1024
#define DMODEL   1024
#define DINNER   2048
#define DSTATE   16
#define NTOK     (BATCH * SEQ)          // 2048
#define XW       (DINNER + 2 * DSTATE)  // 2080
#define NSEG     32
#define GSEG     32

// ---------------- fp32 scratch ----------------
__device__ float g_xn [NTOK * DMODEL];
__device__ float g_xr [NTOK * 2 * DINNER];
__device__ float g_xs [NTOK * DINNER];
__device__ float g_ssm[NTOK * XW];
__device__ float g_dt [NTOK * DINNER];
__device__ float g_yz [NTOK * DINNER];
__device__ float g_P  [BATCH * NSEG * DSTATE * DINNER];
__device__ float g_Q  [BATCH * NSEG * DSTATE * DINNER];
__device__ float g_H  [BATCH * NSEG * DSTATE * DINNER];

// ---------------- bf16 split buffers ----------------
__device__ __nv_bfloat16 g_ah[NTOK * DINNER];
__device__ __nv_bfloat16 g_al[NTOK * DINNER];
__device__ __nv_bfloat16 g_w1h[4096 * 1024], g_w1l[4096 * 1024];   // W_in^T
__device__ __nv_bfloat16 g_w2h[2176 * 2048], g_w2l[2176 * 2048];   // W_x^T (padded)
__device__ __nv_bfloat16 g_w3h[2048 * 2048], g_w3l[2048 * 2048];   // W_dt^T
__device__ __nv_bfloat16 g_w4h[1024 * 2048], g_w4l[1024 * 2048];   // W_out^T

// ---------------- helpers ----------------
__device__ __forceinline__ uint32_t smem_u32(const void* p) {
    uint32_t a;
    asm("{ .reg .u64 t; cvta.to.shared.u64 t, %1; cvt.u32.u64 %0, t; }"
        : "=r"(a) : "l"(p));
    return a;
}
__device__ __forceinline__ void cp_async16s(uint32_t saddr, const void* gptr) {
    asm volatile("cp.async.cg.shared.global [%0], [%1], 16;\n"
                 :: "r"(saddr), "l"(gptr));
}
__device__ __forceinline__ void cp_commit() {
    asm volatile("cp.async.commit_group;\n");
}
__device__ __forceinline__ void ldsm4(uint32_t* r, uint32_t a) {
    asm volatile("ldmatrix.sync.aligned.m8n8.x4.shared.b16 {%0,%1,%2,%3}, [%4];"
                 : "=r"(r[0]), "=r"(r[1]), "=r"(r[2]), "=r"(r[3]) : "r"(a));
}
__device__ __forceinline__ void mma16816(float* c, const uint32_t* a,
                                         const uint32_t* b) {
    asm volatile(
        "mma.sync.aligned.m16n8k16.row.col.f32.bf16.bf16.f32 "
        "{%0,%1,%2,%3}, {%4,%5,%6,%7}, {%8,%9}, {%0,%1,%2,%3};"
        : "+f"(c[0]), "+f"(c[1]), "+f"(c[2]), "+f"(c[3])
        : "r"(a[0]), "r"(a[1]), "r"(a[2]), "r"(a[3]), "r"(b[0]), "r"(b[1]));
}

// ---------------- RMSNorm ----------------
__global__ void rmsnorm_kernel(const float* __restrict__ x,
                               const float* __restrict__ w,
                               float* __restrict__ xn) {
    const int t   = blockIdx.x;
    const int tid = threadIdx.x;
    const float4 v = reinterpret_cast<const float4*>(x + t * DMODEL)[tid];
    float s = v.x * v.x + v.y * v.y + v.z * v.z + v.w * v.w;
    #pragma unroll
    for (int o = 16; o; o >>= 1) s += __shfl_xor_sync(0xffffffffu, s, o);
    __shared__ float red[8];
    __shared__ float sscale;
    if ((tid & 31) == 0) red[tid >> 5] = s;
    __syncthreads();
    if (tid == 0) {
        float tot = 0.f;
        #pragma unroll
        for (int i = 0; i < 8; ++i) tot += red[i];
        sscale = rsqrtf(tot * (1.0f / DMODEL) + 1e-5f);
    }
    __syncthreads();
    const float sc = sscale;
    const float4 wv = reinterpret_cast<const float4*>(w)[tid];
    float4 o;
    o.x = v.x * sc * wv.x;  o.y = v.y * sc * wv.y;
    o.z = v.z * sc * wv.z;  o.w = v.w * sc * wv.w;
    reinterpret_cast<float4*>(xn + t * DMODEL)[tid] = o;
}

// ---------------- depthwise causal conv + SiLU ----------------
__global__ void conv_silu_kernel(const float* __restrict__ xr,
                                 const float* __restrict__ cw,
                                 const float* __restrict__ cb,
                                 float* __restrict__ xs) {
    const int idx = blockIdx.x * blockDim.x + threadIdx.x;
    const int d   = idx & (DINNER - 1);
    const int tok = idx >> 11;
    const int l   = tok & (SEQ - 1);
    float acc = cb[d];
    #pragma unroll
    for (int j = 0; j < 4; ++j) {
        const int ls = l - 3 + j;
        if (ls >= 0)
            acc = fmaf(cw[d * 4 + j], xr[(tok + j - 3) * (2 * DINNER) + d], acc);
    }
    xs[idx] = acc / (1.f + __expf(-acc));
}

// ---------------- split kernels ----------------
__global__ void asplit_kernel(const float* __restrict__ src,
                              __nv_bfloat16* __restrict__ h,
                              __nv_bfloat16* __restrict__ l,
                              int Kp, int lda) {
    const int i = (blockIdx.x * 256 + threadIdx.x) * 2;
    const int m = i / Kp, k = i - m * Kp;
    const float2 v = *reinterpret_cast<const float2*>(&src[m * lda + k]);
    const __nv_bfloat16 hx = __float2bfloat16(v.x);
    const __nv_bfloat16 hy = __float2bfloat16(v.y);
    __nv_bfloat162 hh; hh.x = hx; hh.y = hy;
    __nv_bfloat162 ll;
    ll.x = __float2bfloat16(v.x - __bfloat162float(hx));
    ll.y = __float2bfloat16(v.y - __bfloat162float(hy));
    *reinterpret_cast<__nv_bfloat162*>(&h[i]) = hh;
    *reinterpret_cast<__nv_bfloat162*>(&l[i]) = ll;
}

// weights: fp32 W[K,N] -> bf16 hi/lo transposed [Npad, K] (zero pad rows)
__global__ void wsplit_t_kernel(const float* __restrict__ W,
                                __nv_bfloat16* __restrict__ Th,
                                __nv_bfloat16* __restrict__ Tl,
                                int K, int N) {
    __shared__ float tile[32][33];
    const int n0 = blockIdx.x * 32, k0 = blockIdx.y * 32;
    const int tx = threadIdx.x, ty = threadIdx.y;   // 32 x 8
    #pragma unroll
    for (int r = 0; r < 4; ++r) {
        const int k = k0 + ty + 8 * r, n = n0 + tx;
        tile[ty + 8 * r][tx] = (n < N) ? W[k * N + n] : 0.f;
    }
    __syncthreads();
    #pragma unroll
    for (int r = 0; r < 4; ++r) {
        const int nrow = n0 + ty + 8 * r, k = k0 + tx;
        const float v = tile[tx][ty + 8 * r];
        const __nv_bfloat16 hi = __float2bfloat16(v);
        Th[(size_t)nrow * K + k] = hi;
        Tl[(size_t)nrow * K + k] = __float2bfloat16(v - __bfloat162float(hi));
    }
}

// ---------------- mma.sync bf16-split GEMM ----------------
// D[2048, N] = act( A @ B^T ), A split (Ah,Al)[2048,K], B split (Bh,Bl)[Npad,K].
// CTA tile 128x128, 8 warps (warp tile 64x32), K-chunk 32, 3-stage cp.async.
// smem layout per stage (32KB): Ah | Al | Bh | Bl, each 128 rows x 32 bf16.
// byte addr within a tile: row*64 + ((gran ^ ((row>>1)&3)) << 4), gran = k16B-granule.
#define TCK 32
#define STAGE_BYTES 32768
#define SMEM_TC (3 * STAGE_BYTES)

#define ACT_NONE     0
#define ACT_SOFTPLUS 1
#define ACT_RESADD   2

template <int ACT>
__global__ __launch_bounds__(256, 1)
void tcgemm_kernel(const __nv_bfloat16* __restrict__ Ah,
                   const __nv_bfloat16* __restrict__ Al,
                   const __nv_bfloat16* __restrict__ Bh,
                   const __nv_bfloat16* __restrict__ Bl,
                   float* __restrict__ D, const float* __restrict__ Res,
                   int N, int K, int ldd, int ldr) {
    extern __shared__ unsigned char sm[];
    const uint32_t smb = smem_u32(sm);

    const int tid  = threadIdx.x;
    const int lane = tid & 31;
    const int wid  = tid >> 5;
    const int wm   = wid >> 2;      // 0..1 : 64-row band
    const int wn   = wid & 3;       // 0..3 : 32-col band
    const int m0   = blockIdx.y * 128;
    const int n0   = blockIdx.x * 128;

    // ---- cp.async geometry: thread -> (row, 2 granules)
    const int lrow = tid >> 1;              // 0..127
    const int gp   = (tid & 1) * 2;         // 0 or 2
    const int swl  = (lrow >> 1) & 3;
    const uint32_t dst0 = lrow * 64 + (((gp + 0) ^ swl) << 4);
    const uint32_t dst1 = lrow * 64 + (((gp + 1) ^ swl) << 4);
    const __nv_bfloat16* srcs[4] = {
        Ah + (size_t)(m0 + lrow) * K + gp * 8,
        Al + (size_t)(m0 + lrow) * K + gp * 8,
        Bh + (size_t)(n0 + lrow) * K + gp * 8,
        Bl + (size_t)(n0 + lrow) * K + gp * 8 };

    // ---- ldmatrix geometry
    // A (no-trans x4, one m16 tile per call): lanes 0-7 rows 0-7 g0, 8-15 rows 8-15 g0,
    //   16-23 rows 0-7 g1, 24-31 rows 8-15 g1  -> regs = a0..a3.
    const int agsel = lane >> 4;
    const int rowA  = wm * 64 + (lane & 15);
    const uint32_t offA = rowA * 64 + ((agsel ^ ((rowA >> 1) & 3)) << 4);
    // B (no-trans x4, two n8 tiles per call): lanes 0-7 rows n0-7 g0, 8-15 rows n0-7 g1,
    //   16-23 rows n8-15 g0, 24-31 rows n8-15 g1 -> regs = b0,b1 (tile0), b0,b1 (tile1).
    const int nr    = (lane & 7) + ((lane >> 4) << 3);
    const int kgsel = (lane >> 3) & 1;
    const int rowB  = wn * 32 + nr;
    const uint32_t offB = 16384 + rowB * 64 + ((kgsel ^ ((rowB >> 1) & 3)) << 4);

    const int T = K / TCK;

#define LOAD_CHUNK(STAGE, K0) do {                                        \
        const uint32_t sb_ = smb + (STAGE) * STAGE_BYTES;                 \
        _Pragma("unroll")                                                 \
        for (int mx = 0; mx < 4; ++mx) {                                  \
            cp_async16s(sb_ + mx * 8192 + dst0, srcs[mx] + (K0));         \
            cp_async16s(sb_ + mx * 8192 + dst1, srcs[mx] + (K0) + 8);     \
        }                                                                 \
        cp_commit();                                                      \
    } while (0)

    LOAD_CHUNK(0, 0);
    LOAD_CHUNK(1, TCK);

    float acc[4][4][4];
    #pragma unroll
    for (int t = 0; t < 4; ++t)
        #pragma unroll
        for (int j = 0; j < 4; ++j)
            #pragma unroll
            for (int q = 0; q < 4; ++q) acc[t][j][q] = 0.f;

    for (int i = 0; i < T; ++i) {
        asm volatile("cp.async.wait_group 1;\n" ::: "memory");
        __syncthreads();   // chunk i resident; everyone done with buffer (i+2)%3

        if (i + 2 < T) LOAD_CHUNK((i + 2) % 3, (size_t)(i + 2) * TCK);
        else           cp_commit();   // keep group counting aligned

        const uint32_t sb = smb + (i % 3) * STAGE_BYTES;
        #pragma unroll
        for (int ks = 0; ks < 2; ++ks) {
            const uint32_t kx = ks * 32;   // XOR-toggle of the 16B-granule bit
            uint32_t ah_[4][4], al_[4][4], bh_[2][4], bl_[2][4];
            #pragma unroll
            for (int t = 0; t < 4; ++t) {
                const uint32_t oa = (offA + t * 1024) ^ kx;
                ldsm4(ah_[t], sb + oa);
                ldsm4(al_[t], sb + 8192 + oa);
            }
            #pragma unroll
            for (int p = 0; p < 2; ++p) {
                const uint32_t ob = (offB + p * 1024) ^ kx;
                ldsm4(bh_[p], sb + ob);
                ldsm4(bl_[p], sb + 8192 + ob);
            }
            #pragma unroll
            for (int t = 0; t < 4; ++t)
                #pragma unroll
                for (int j = 0; j < 4; ++j) {
                    mma16816(acc[t][j], ah_[t], &bh_[j >> 1][(j & 1) * 2]);
                    mma16816(acc[t][j], al_[t], &bh_[j >> 1][(j & 1) * 2]);
                    mma16816(acc[t][j], ah_[t], &bl_[j >> 1][(j & 1) * 2]);
                }
        }
    }
#undef LOAD_CHUNK

    // ---- epilogue: c0,c1 -> (row, col..col+1); c2,c3 -> (row+8, col..col+1)
    const int g  = lane >> 2;
    const int tg = lane & 3;
    #pragma unroll
    for (int t = 0; t < 4; ++t) {
        const int row = m0 + wm * 64 + t * 16 + g;
        #pragma unroll
        for (int j = 0; j < 4; ++j) {
            const int col = n0 + wn * 32 + j * 8 + 2 * tg;
            if (col < N) {
                float c0 = acc[t][j][0], c1 = acc[t][j][1];
                float c2 = acc[t][j][2], c3 = acc[t][j][3];
                if (ACT == ACT_SOFTPLUS) {
                    c0 = fmaxf(c0, 0.f) + log1pf(__expf(-fabsf(c0)));
                    c1 = fmaxf(c1, 0.f) + log1pf(__expf(-fabsf(c1)));
                    c2 = fmaxf(c2, 0.f) + log1pf(__expf(-fabsf(c2)));
                    c3 = fmaxf(c3, 0.f) + log1pf(__expf(-fabsf(c3)));
                }
                if (ACT == ACT_RESADD) {
                    const float2 r0 = *reinterpret_cast<const float2*>(
                        &Res[(size_t)row * ldr + col]);
                    const float2 r1 = *reinterpret_cast<const float2*>(
                        &Res[(size_t)(row + 8) * ldr + col]);
                    c0 += r0.x; c1 += r0.y; c2 += r1.x; c3 += r1.y;
                }
                *reinterpret_cast<float2*>(&D[(size_t)row * ldd + col]) =
                    make_float2(c0, c1);
                *reinterpret_cast<float2*>(&D[(size_t)(row + 8) * ldd + col]) =
                    make_float2(c2, c3);
            }
        }
    }
}

// ---------------- chunked parallel selective scan ----------------
__global__ __launch_bounds__(256)
void scan_p1(const float* __restrict__ dt, const float* __restrict__ xs,
             const float* __restrict__ ssm, const float* __restrict__ A_log,
             float* __restrict__ P, float* __restrict__ Q) {
    __shared__ float Bsh[GSEG][DSTATE];
    const int b = blockIdx.z, s = blockIdx.y;
    const int d = blockIdx.x * 256 + threadIdx.x;
    const int tok0 = b * SEQ + s * GSEG;

    for (int v = threadIdx.x; v < GSEG * DSTATE; v += 256) {
        const int l = v >> 4, n = v & 15;
        Bsh[l][n] = ssm[(tok0 + l) * XW + DINNER + n];
    }
    __syncthreads();

    float Ac[DSTATE];
    #pragma unroll
    for (int q = 0; q < 4; ++q) {
        const float4 v = reinterpret_cast<const float4*>(&A_log[d * DSTATE])[q];
        Ac[4 * q + 0] = -__expf(v.x);  Ac[4 * q + 1] = -__expf(v.y);
        Ac[4 * q + 2] = -__expf(v.z);  Ac[4 * q + 3] = -__expf(v.w);
    }

    float h[DSTATE];
    #pragma unroll
    for (int n = 0; n < DSTATE; ++n) h[n] = 0.f;
    float sdt = 0.f;

    for (int l = 0; l < GSEG; ++l) {
        const float dtv = dt[(tok0 + l) * DINNER + d];
        const float xv  = xs[(tok0 + l) * DINNER + d];
        sdt += dtv;
        const float dtx = dtv * xv;
        #pragma unroll
        for (int n = 0; n < DSTATE; ++n)
            h[n] = fmaf(__expf(Ac[n] * dtv), h[n], dtx * Bsh[l][n]);
    }

    const int basei = ((b * NSEG + s) * DSTATE) * DINNER + d;
    #pragma unroll
    for (int n = 0; n < DSTATE; ++n) {
        P[basei + n * DINNER] = __expf(Ac[n] * sdt);
        Q[basei + n * DINNER] = h[n];
    }
}

__global__ void scan_combine(const float* __restrict__ P,
                             const float* __restrict__ Q,
                             float* __restrict__ H) {
    const int t = blockIdx.x * 256 + threadIdx.x;
    const int d = t & (DINNER - 1);
    const int n = (t >> 11) & 15;
    const int b = t >> 15;
    float h = 0.f;
    for (int s = 0; s < NSEG; ++s) {
        const int off = ((b * NSEG + s) * DSTATE + n) * DINNER + d;
        H[off] = h;
        h = fmaf(P[off], h, Q[off]);
    }
}

__global__ __launch_bounds__(256)
void scan_p2(const float* __restrict__ dt, const float* __restrict__ xs,
             const float* __restrict__ ssm, const float* __restrict__ xr,
             const float* __restrict__ A_log, const float* __restrict__ H,
             float* __restrict__ yz) {
    __shared__ float Bsh[GSEG][DSTATE];
    __shared__ float Csh[GSEG][DSTATE];
    const int b = blockIdx.z, s = blockIdx.y;
    const int d = blockIdx.x * 256 + threadIdx.x;
    const int tok0 = b * SEQ + s * GSEG;

    for (int v = threadIdx.x; v < GSEG * DSTATE * 2; v += 256) {
        const int l = v >> 5, j = v & 31;
        const float val = ssm[(tok0 + l) * XW + DINNER + j];
        if (j < DSTATE) Bsh[l][j] = val;
        else            Csh[l][j - DSTATE] = val;
    }
    __syncthreads();

    float Ac[DSTATE];
    #pragma unroll
    for (int q = 0; q < 4; ++q) {
        const float4 v = reinterpret_cast<const float4*>(&A_log[d * DSTATE])[q];
        Ac[4 * q + 0] = -__expf(v.x);  Ac[4 * q + 1] = -__expf(v.y);
        Ac[4 * q + 2] = -__expf(v.z);  Ac[4 * q + 3] = -__expf(v.w);
    }

    const int basei = ((b * NSEG + s) * DSTATE) * DINNER + d;
    float h[DSTATE];
    #pragma unroll
    for (int n = 0; n < DSTATE; ++n) h[n] = H[basei + n * DINNER];

    for (int l = 0; l < GSEG; ++l) {
        const float dtv = dt[(tok0 + l) * DINNER + d];
        const float xv  = xs[(tok0 + l) * DINNER + d];
        const float dtx = dtv * xv;
        float y = 0.f;
        #pragma unroll
        for (int n = 0; n < DSTATE; ++n) {
            h[n] = fmaf(__expf(Ac[n] * dtv), h[n], dtx * Bsh[l][n]);
            y = fmaf(h[n], Csh[l][n], y);
        }
        const float r = xr[(tok0 + l) * (2 * DINNER) + DINNER + d];
        yz[(tok0 + l) * DINNER + d] = y * (r / (1.f + __expf(-r)));
    }
}

// ---------------- launch ----------------
extern "C" void kernel_launch(void* const* d_in, const int* in_sizes, int n_in,
                              void* d_out, int out_size) {
    const float* x      = (const float*)d_in[0];
    const float* rms_w  = (const float*)d_in[1];
    const float* W_in   = (const float*)d_in[2];
    const float* conv_w = (const float*)d_in[3];
    const float* conv_b = (const float*)d_in[4];
    const float* W_x    = (const float*)d_in[5];
    const float* W_dt   = (const float*)d_in[6];
    const float* A_log  = (const float*)d_in[7];
    const float* W_out  = (const float*)d_in[8];
    float* out = (float*)d_out;

    float *xn, *xr, *xs, *ssm, *dtb, *yz, *P, *Q, *H;
    __nv_bfloat16 *ah, *al, *w1h, *w1l, *w2h, *w2l, *w3h, *w3l, *w4h, *w4l;
    cudaGetSymbolAddress((void**)&xn,  g_xn);
    cudaGetSymbolAddress((void**)&xr,  g_xr);
    cudaGetSymbolAddress((void**)&xs,  g_xs);
    cudaGetSymbolAddress((void**)&ssm, g_ssm);
    cudaGetSymbolAddress((void**)&dtb, g_dt);
    cudaGetSymbolAddress((void**)&yz,  g_yz);
    cudaGetSymbolAddress((void**)&P,   g_P);
    cudaGetSymbolAddress((void**)&Q,   g_Q);
    cudaGetSymbolAddress((void**)&H,   g_H);
    cudaGetSymbolAddress((void**)&ah,  g_ah);
    cudaGetSymbolAddress((void**)&al,  g_al);
    cudaGetSymbolAddress((void**)&w1h, g_w1h);  cudaGetSymbolAddress((void**)&w1l, g_w1l);
    cudaGetSymbolAddress((void**)&w2h, g_w2h);  cudaGetSymbolAddress((void**)&w2l, g_w2l);
    cudaGetSymbolAddress((void**)&w3h, g_w3h);  cudaGetSymbolAddress((void**)&w3l, g_w3l);
    cudaGetSymbolAddress((void**)&w4h, g_w4h);  cudaGetSymbolAddress((void**)&w4l, g_w4l);

    static bool attr_done = false;
    if (!attr_done) {
        cudaFuncSetAttribute(tcgemm_kernel<ACT_NONE>,
            cudaFuncAttributeMaxDynamicSharedMemorySize, SMEM_TC);
        cudaFuncSetAttribute(tcgemm_kernel<ACT_SOFTPLUS>,
            cudaFuncAttributeMaxDynamicSharedMemorySize, SMEM_TC);
        cudaFuncSetAttribute(tcgemm_kernel<ACT_RESADD>,
            cudaFuncAttributeMaxDynamicSharedMemorySize, SMEM_TC);
        attr_done = true;
    }

    const dim3 tb(32, 8);

    // weight split+transpose
    wsplit_t_kernel<<<dim3(4096 / 32, 1024 / 32), tb>>>(W_in,  w1h, w1l, 1024, 4096);
    wsplit_t_kernel<<<dim3(2176 / 32, 2048 / 32), tb>>>(W_x,   w2h, w2l, 2048, XW);
    wsplit_t_kernel<<<dim3(2048 / 32, 2048 / 32), tb>>>(W_dt,  w3h, w3l, 2048, 2048);
    wsplit_t_kernel<<<dim3(1024 / 32, 2048 / 32), tb>>>(W_out, w4h, w4l, 2048, 1024);

    // 1. RMSNorm
    rmsnorm_kernel<<<NTOK, 256>>>(x, rms_w, xn);

    // 2. xr = xn @ W_in   [2048,4096], K=1024
    asplit_kernel<<<(NTOK * DMODEL / 2) / 256, 256>>>(xn, ah, al, DMODEL, DMODEL);
    tcgemm_kernel<ACT_NONE><<<dim3(32, 16), 256, SMEM_TC>>>(
        ah, al, w1h, w1l, xr, nullptr, 4096, 1024, 4096, 0);

    // 3. conv + silu
    conv_silu_kernel<<<(NTOK * DINNER) / 256, 256>>>(xr, conv_w, conv_b, xs);

    // 4. x_ssm = xs @ W_x   [2048,2080], K=2048
    asplit_kernel<<<(NTOK * DINNER / 2) / 256, 256>>>(xs, ah, al, DINNER, DINNER);
    tcgemm_kernel<ACT_NONE><<<dim3(17, 16), 256, SMEM_TC>>>(
        ah, al, w2h, w2l, ssm, nullptr, XW, 2048, XW, 0);

    // 5. dt = softplus(ssm[:, :2048] @ W_dt)   K=2048
    asplit_kernel<<<(NTOK * DINNER / 2) / 256, 256>>>(ssm, ah, al, DINNER, XW);
    tcgemm_kernel<ACT_SOFTPLUS><<<dim3(16, 16), 256, SMEM_TC>>>(
        ah, al, w3h, w3l, dtb, nullptr, 2048, 2048, 2048, 0);

    // 6. chunked parallel scan
    scan_p1<<<dim3(DINNER / 256, NSEG, BATCH), 256>>>(dtb, xs, ssm, A_log, P, Q);
    scan_combine<<<(BATCH * DSTATE * DINNER) / 256, 256>>>(P, Q, H);
    scan_p2<<<dim3(DINNER / 256, NSEG, BATCH), 256>>>(dtb, xs, ssm, xr, A_log, H, yz);

    // 7. out = x + yz @ W_out   [2048,1024], K=2048
    asplit_kernel<<<(NTOK * DINNER / 2) / 256, 256>>>(yz, ah, al, DINNER, DINNER);
    tcgemm_kernel<ACT_RESADD><<<dim3(8, 16), 256, SMEM_TC>>>(
        ah, al, w4h, w4l, out, x, 1024, 2048, 1024, 1024);
}

// round 8
// speedup vs baseline: 2.1974x; 1.1341x over previous
#include <cuda_runtime.h>
#include <cuda_bf16.h>
#include <math.h>
#include <stdint.h>

// ---------------- problem constants ----------------
#define BATCH    2
#define SEQ      1024
#define DMODEL   1024
#define DINNER   2048
#define DSTATE   16
#define NTOK     (BATCH * SEQ)          // 2048
#define XW       (DINNER + 2 * DSTATE)  // 2080
#define NSEG     32
#define GSEG     32

// ---------------- fp32 scratch ----------------
__device__ float g_xr [NTOK * 2 * DINNER];
__device__ float g_xs [NTOK * DINNER];
__device__ float g_ssm[NTOK * XW];
__device__ float g_dt [NTOK * DINNER];
__device__ float g_P  [BATCH * NSEG * DSTATE * DINNER];
__device__ float g_Q  [BATCH * NSEG * DSTATE * DINNER];
__device__ float g_H  [BATCH * NSEG * DSTATE * DINNER];

// ---------------- bf16 split buffers (two ping-pong A pairs) ----------------
__device__ __nv_bfloat16 g_ah0[NTOK * DINNER], g_al0[NTOK * DINNER];
__device__ __nv_bfloat16 g_ah1[NTOK * DINNER], g_al1[NTOK * DINNER];
__device__ __nv_bfloat16 g_w1h[4096 * 1024], g_w1l[4096 * 1024];   // W_in^T
__device__ __nv_bfloat16 g_w2h[2176 * 2048], g_w2l[2176 * 2048];   // W_x^T (padded)
__device__ __nv_bfloat16 g_w3h[2048 * 2048], g_w3l[2048 * 2048];   // W_dt^T
__device__ __nv_bfloat16 g_w4h[1024 * 2048], g_w4l[1024 * 2048];   // W_out^T

// ---------------- helpers ----------------
__device__ __forceinline__ uint32_t smem_u32(const void* p) {
    uint32_t a;
    asm("{ .reg .u64 t; cvta.to.shared.u64 t, %1; cvt.u32.u64 %0, t; }"
        : "=r"(a) : "l"(p));
    return a;
}
__device__ __forceinline__ void cp_async16s(uint32_t saddr, const void* gptr) {
    asm volatile("cp.async.cg.shared.global [%0], [%1], 16;\n"
                 :: "r"(saddr), "l"(gptr));
}
__device__ __forceinline__ void cp_commit() {
    asm volatile("cp.async.commit_group;\n");
}
__device__ __forceinline__ void ldsm4(uint32_t* r, uint32_t a) {
    asm volatile("ldmatrix.sync.aligned.m8n8.x4.shared.b16 {%0,%1,%2,%3}, [%4];"
                 : "=r"(r[0]), "=r"(r[1]), "=r"(r[2]), "=r"(r[3]) : "r"(a));
}
__device__ __forceinline__ void mma16816(float* c, const uint32_t* a,
                                         const uint32_t* b) {
    asm volatile(
        "mma.sync.aligned.m16n8k16.row.col.f32.bf16.bf16.f32 "
        "{%0,%1,%2,%3}, {%4,%5,%6,%7}, {%8,%9}, {%0,%1,%2,%3};"
        : "+f"(c[0]), "+f"(c[1]), "+f"(c[2]), "+f"(c[3])
        : "r"(a[0]), "r"(a[1]), "r"(a[2]), "r"(a[3]), "r"(b[0]), "r"(b[1]));
}
__device__ __forceinline__ void split2(__nv_bfloat16* h, __nv_bfloat16* l,
                                       float v0, float v1) {
    const __nv_bfloat16 h0 = __float2bfloat16(v0);
    const __nv_bfloat16 h1 = __float2bfloat16(v1);
    __nv_bfloat162 hh; hh.x = h0; hh.y = h1;
    __nv_bfloat162 ll;
    ll.x = __float2bfloat16(v0 - __bfloat162float(h0));
    ll.y = __float2bfloat16(v1 - __bfloat162float(h1));
    *reinterpret_cast<__nv_bfloat162*>(h) = hh;
    *reinterpret_cast<__nv_bfloat162*>(l) = ll;
}

// ---------------- RMSNorm, split output ----------------
__global__ void rmsnorm_split_kernel(const float* __restrict__ x,
                                     const float* __restrict__ w,
                                     __nv_bfloat16* __restrict__ oh,
                                     __nv_bfloat16* __restrict__ ol) {
    const int t   = blockIdx.x;
    const int tid = threadIdx.x;
    const float4 v = reinterpret_cast<const float4*>(x + t * DMODEL)[tid];
    float s = v.x * v.x + v.y * v.y + v.z * v.z + v.w * v.w;
    #pragma unroll
    for (int o = 16; o; o >>= 1) s += __shfl_xor_sync(0xffffffffu, s, o);
    __shared__ float red[8];
    __shared__ float sscale;
    if ((tid & 31) == 0) red[tid >> 5] = s;
    __syncthreads();
    if (tid == 0) {
        float tot = 0.f;
        #pragma unroll
        for (int i = 0; i < 8; ++i) tot += red[i];
        sscale = rsqrtf(tot * (1.0f / DMODEL) + 1e-5f);
    }
    __syncthreads();
    const float sc = sscale;
    const float4 wv = reinterpret_cast<const float4*>(w)[tid];
    const int base = t * DMODEL + tid * 4;
    split2(&oh[base],     &ol[base],     v.x * sc * wv.x, v.y * sc * wv.y);
    split2(&oh[base + 2], &ol[base + 2], v.z * sc * wv.z, v.w * sc * wv.w);
}

// ---------------- depthwise causal conv + SiLU, fp32 + split out ----------------
__global__ void conv_silu_kernel(const float* __restrict__ xr,
                                 const float* __restrict__ cw,
                                 const float* __restrict__ cb,
                                 float* __restrict__ xs,
                                 __nv_bfloat16* __restrict__ oh,
                                 __nv_bfloat16* __restrict__ ol) {
    const int idx = (blockIdx.x * blockDim.x + threadIdx.x) * 2;  // 2 elems/thread
    const int d   = idx & (DINNER - 1);
    const int tok = idx >> 11;
    const int l   = tok & (SEQ - 1);
    float a0 = cb[d], a1 = cb[d + 1];
    #pragma unroll
    for (int j = 0; j < 4; ++j) {
        const int ls = l - 3 + j;
        if (ls >= 0) {
            const float2 xv = *reinterpret_cast<const float2*>(
                &xr[(tok + j - 3) * (2 * DINNER) + d]);
            a0 = fmaf(cw[d * 4 + j],       xv.x, a0);
            a1 = fmaf(cw[(d + 1) * 4 + j], xv.y, a1);
        }
    }
    a0 = a0 / (1.f + __expf(-a0));
    a1 = a1 / (1.f + __expf(-a1));
    *reinterpret_cast<float2*>(&xs[idx]) = make_float2(a0, a1);
    split2(&oh[idx], &ol[idx], a0, a1);
}

// ---------------- weight split+transpose ----------------
__global__ void wsplit_t_kernel(const float* __restrict__ W,
                                __nv_bfloat16* __restrict__ Th,
                                __nv_bfloat16* __restrict__ Tl,
                                int K, int N) {
    __shared__ float tile[32][33];
    const int n0 = blockIdx.x * 32, k0 = blockIdx.y * 32;
    const int tx = threadIdx.x, ty = threadIdx.y;   // 32 x 8
    #pragma unroll
    for (int r = 0; r < 4; ++r) {
        const int k = k0 + ty + 8 * r, n = n0 + tx;
        tile[ty + 8 * r][tx] = (n < N) ? W[k * N + n] : 0.f;
    }
    __syncthreads();
    #pragma unroll
    for (int r = 0; r < 4; ++r) {
        const int nrow = n0 + ty + 8 * r, k = k0 + tx;
        const float v = tile[tx][ty + 8 * r];
        const __nv_bfloat16 hi = __float2bfloat16(v);
        Th[(size_t)nrow * K + k] = hi;
        Tl[(size_t)nrow * K + k] = __float2bfloat16(v - __bfloat162float(hi));
    }
}

// ---------------- mma.sync bf16-split GEMM ----------------
// CTA tile 128x128, 8 warps (warp tile 64x32), K-chunk 32, 3-stage cp.async.
// 2 CTAs/SM target: B frags loaded per n-slice to keep regs under 128.
#define TCK 32
#define STAGE_BYTES 32768
#define SMEM_TC (3 * STAGE_BYTES)

#define ACT_NONE     0
#define ACT_SOFTPLUS 1
#define ACT_RESADD   2

template <int ACT, int SPLIT>
__global__ __launch_bounds__(256, 2)
void tcgemm_kernel(const __nv_bfloat16* __restrict__ Ah,
                   const __nv_bfloat16* __restrict__ Al,
                   const __nv_bfloat16* __restrict__ Bh,
                   const __nv_bfloat16* __restrict__ Bl,
                   float* __restrict__ D, const float* __restrict__ Res,
                   __nv_bfloat16* __restrict__ Sh, __nv_bfloat16* __restrict__ Sl,
                   int N, int K, int ldd, int ldr) {
    extern __shared__ unsigned char sm[];
    const uint32_t smb = smem_u32(sm);

    const int tid  = threadIdx.x;
    const int lane = tid & 31;
    const int wid  = tid >> 5;
    const int wm   = wid >> 2;
    const int wn   = wid & 3;
    const int m0   = blockIdx.y * 128;
    const int n0   = blockIdx.x * 128;

    // cp.async geometry
    const int lrow = tid >> 1;
    const int gp   = (tid & 1) * 2;
    const int swl  = (lrow >> 1) & 3;
    const uint32_t dst0 = lrow * 64 + (((gp + 0) ^ swl) << 4);
    const uint32_t dst1 = lrow * 64 + (((gp + 1) ^ swl) << 4);
    const __nv_bfloat16* srcs[4] = {
        Ah + (size_t)(m0 + lrow) * K + gp * 8,
        Al + (size_t)(m0 + lrow) * K + gp * 8,
        Bh + (size_t)(n0 + lrow) * K + gp * 8,
        Bl + (size_t)(n0 + lrow) * K + gp * 8 };

    // ldmatrix geometry (identical to validated R6 layout)
    const int agsel = lane >> 4;
    const int rowA  = wm * 64 + (lane & 15);
    const uint32_t offA = rowA * 64 + ((agsel ^ ((rowA >> 1) & 3)) << 4);
    const int nr    = (lane & 7) + ((lane >> 4) << 3);
    const int kgsel = (lane >> 3) & 1;
    const int rowB  = wn * 32 + nr;
    const uint32_t offB = 16384 + rowB * 64 + ((kgsel ^ ((rowB >> 1) & 3)) << 4);

    const int T = K / TCK;

#define LOAD_CHUNK(STAGE, K0) do {                                        \
        const uint32_t sb_ = smb + (STAGE) * STAGE_BYTES;                 \
        _Pragma("unroll")                                                 \
        for (int mx = 0; mx < 4; ++mx) {                                  \
            cp_async16s(sb_ + mx * 8192 + dst0, srcs[mx] + (K0));         \
            cp_async16s(sb_ + mx * 8192 + dst1, srcs[mx] + (K0) + 8);     \
        }                                                                 \
        cp_commit();                                                      \
    } while (0)

    LOAD_CHUNK(0, 0);
    LOAD_CHUNK(1, TCK);

    float acc[4][4][4];
    #pragma unroll
    for (int t = 0; t < 4; ++t)
        #pragma unroll
        for (int j = 0; j < 4; ++j)
            #pragma unroll
            for (int q = 0; q < 4; ++q) acc[t][j][q] = 0.f;

    for (int i = 0; i < T; ++i) {
        asm volatile("cp.async.wait_group 1;\n" ::: "memory");
        __syncthreads();

        if (i + 2 < T) LOAD_CHUNK((i + 2) % 3, (size_t)(i + 2) * TCK);
        else           cp_commit();

        const uint32_t sb = smb + (i % 3) * STAGE_BYTES;
        #pragma unroll
        for (int ks = 0; ks < 2; ++ks) {
            const uint32_t kx = ks * 32;
            uint32_t ah_[4][4], al_[4][4];
            #pragma unroll
            for (int t = 0; t < 4; ++t) {
                const uint32_t oa = (offA + t * 1024) ^ kx;
                ldsm4(ah_[t], sb + oa);
                ldsm4(al_[t], sb + 8192 + oa);
            }
            #pragma unroll
            for (int p = 0; p < 2; ++p) {
                uint32_t bh_[4], bl_[4];
                const uint32_t ob = (offB + p * 1024) ^ kx;
                ldsm4(bh_, sb + ob);
                ldsm4(bl_, sb + 8192 + ob);
                #pragma unroll
                for (int t = 0; t < 4; ++t) {
                    mma16816(acc[t][2 * p],     ah_[t], bh_);
                    mma16816(acc[t][2 * p],     al_[t], bh_);
                    mma16816(acc[t][2 * p],     ah_[t], bl_);
                    mma16816(acc[t][2 * p + 1], ah_[t], bh_ + 2);
                    mma16816(acc[t][2 * p + 1], al_[t], bh_ + 2);
                    mma16816(acc[t][2 * p + 1], ah_[t], bl_ + 2);
                }
            }
        }
    }
#undef LOAD_CHUNK

    // ---- epilogue
    const int g  = lane >> 2;
    const int tg = lane & 3;
    #pragma unroll
    for (int t = 0; t < 4; ++t) {
        const int row = m0 + wm * 64 + t * 16 + g;
        #pragma unroll
        for (int j = 0; j < 4; ++j) {
            const int col = n0 + wn * 32 + j * 8 + 2 * tg;
            if (col < N) {
                float c0 = acc[t][j][0], c1 = acc[t][j][1];
                float c2 = acc[t][j][2], c3 = acc[t][j][3];
                if (ACT == ACT_SOFTPLUS) {
                    c0 = fmaxf(c0, 0.f) + log1pf(__expf(-fabsf(c0)));
                    c1 = fmaxf(c1, 0.f) + log1pf(__expf(-fabsf(c1)));
                    c2 = fmaxf(c2, 0.f) + log1pf(__expf(-fabsf(c2)));
                    c3 = fmaxf(c3, 0.f) + log1pf(__expf(-fabsf(c3)));
                }
                if (ACT == ACT_RESADD) {
                    const float2 r0 = *reinterpret_cast<const float2*>(
                        &Res[(size_t)row * ldr + col]);
                    const float2 r1 = *reinterpret_cast<const float2*>(
                        &Res[(size_t)(row + 8) * ldr + col]);
                    c0 += r0.x; c1 += r0.y; c2 += r1.x; c3 += r1.y;
                }
                *reinterpret_cast<float2*>(&D[(size_t)row * ldd + col]) =
                    make_float2(c0, c1);
                *reinterpret_cast<float2*>(&D[(size_t)(row + 8) * ldd + col]) =
                    make_float2(c2, c3);
                if (SPLIT && col < DINNER) {
                    split2(&Sh[(size_t)row * DINNER + col],
                           &Sl[(size_t)row * DINNER + col], c0, c1);
                    split2(&Sh[(size_t)(row + 8) * DINNER + col],
                           &Sl[(size_t)(row + 8) * DINNER + col], c2, c3);
                }
            }
        }
    }
}

// ---------------- chunked parallel selective scan ----------------
__global__ __launch_bounds__(256)
void scan_p1(const float* __restrict__ dt, const float* __restrict__ xs,
             const float* __restrict__ ssm, const float* __restrict__ A_log,
             float* __restrict__ P, float* __restrict__ Q) {
    __shared__ float Bsh[GSEG][DSTATE];
    const int b = blockIdx.z, s = blockIdx.y;
    const int d = blockIdx.x * 256 + threadIdx.x;
    const int tok0 = b * SEQ + s * GSEG;

    for (int v = threadIdx.x; v < GSEG * DSTATE; v += 256) {
        const int l = v >> 4, n = v & 15;
        Bsh[l][n] = ssm[(tok0 + l) * XW + DINNER + n];
    }
    __syncthreads();

    float Ac[DSTATE];
    #pragma unroll
    for (int q = 0; q < 4; ++q) {
        const float4 v = reinterpret_cast<const float4*>(&A_log[d * DSTATE])[q];
        Ac[4 * q + 0] = -__expf(v.x);  Ac[4 * q + 1] = -__expf(v.y);
        Ac[4 * q + 2] = -__expf(v.z);  Ac[4 * q + 3] = -__expf(v.w);
    }

    float h[DSTATE];
    #pragma unroll
    for (int n = 0; n < DSTATE; ++n) h[n] = 0.f;
    float sdt = 0.f;

    for (int l = 0; l < GSEG; ++l) {
        const float dtv = dt[(tok0 + l) * DINNER + d];
        const float xv  = xs[(tok0 + l) * DINNER + d];
        sdt += dtv;
        const float dtx = dtv * xv;
        #pragma unroll
        for (int n = 0; n < DSTATE; ++n)
            h[n] = fmaf(__expf(Ac[n] * dtv), h[n], dtx * Bsh[l][n]);
    }

    const int basei = ((b * NSEG + s) * DSTATE) * DINNER + d;
    #pragma unroll
    for (int n = 0; n < DSTATE; ++n) {
        P[basei + n * DINNER] = __expf(Ac[n] * sdt);
        Q[basei + n * DINNER] = h[n];
    }
}

__global__ void scan_combine(const float* __restrict__ P,
                             const float* __restrict__ Q,
                             float* __restrict__ H) {
    const int t = blockIdx.x * 256 + threadIdx.x;
    const int d = t & (DINNER - 1);
    const int n = (t >> 11) & 15;
    const int b = t >> 15;
    float h = 0.f;
    for (int s = 0; s < NSEG; ++s) {
        const int off = ((b * NSEG + s) * DSTATE + n) * DINNER + d;
        H[off] = h;
        h = fmaf(P[off], h, Q[off]);
    }
}

// pass 2 writes SPLIT yz (bf16 hi/lo) directly for the out-proj GEMM
__global__ __launch_bounds__(256)
void scan_p2(const float* __restrict__ dt, const float* __restrict__ xs,
             const float* __restrict__ ssm, const float* __restrict__ xr,
             const float* __restrict__ A_log, const float* __restrict__ H,
             __nv_bfloat16* __restrict__ yh, __nv_bfloat16* __restrict__ yl) {
    __shared__ float Bsh[GSEG][DSTATE];
    __shared__ float Csh[GSEG][DSTATE];
    const int b = blockIdx.z, s = blockIdx.y;
    const int d = blockIdx.x * 256 + threadIdx.x;
    const int tok0 = b * SEQ + s * GSEG;

    for (int v = threadIdx.x; v < GSEG * DSTATE * 2; v += 256) {
        const int l = v >> 5, j = v & 31;
        const float val = ssm[(tok0 + l) * XW + DINNER + j];
        if (j < DSTATE) Bsh[l][j] = val;
        else            Csh[l][j - DSTATE] = val;
    }
    __syncthreads();

    float Ac[DSTATE];
    #pragma unroll
    for (int q = 0; q < 4; ++q) {
        const float4 v = reinterpret_cast<const float4*>(&A_log[d * DSTATE])[q];
        Ac[4 * q + 0] = -__expf(v.x);  Ac[4 * q + 1] = -__expf(v.y);
        Ac[4 * q + 2] = -__expf(v.z);  Ac[4 * q + 3] = -__expf(v.w);
    }

    const int basei = ((b * NSEG + s) * DSTATE) * DINNER + d;
    float h[DSTATE];
    #pragma unroll
    for (int n = 0; n < DSTATE; ++n) h[n] = H[basei + n * DINNER];

    for (int l = 0; l < GSEG; ++l) {
        const float dtv = dt[(tok0 + l) * DINNER + d];
        const float xv  = xs[(tok0 + l) * DINNER + d];
        const float dtx = dtv * xv;
        float y = 0.f;
        #pragma unroll
        for (int n = 0; n < DSTATE; ++n) {
            h[n] = fmaf(__expf(Ac[n] * dtv), h[n], dtx * Bsh[l][n]);
            y = fmaf(h[n], Csh[l][n], y);
        }
        const float r = xr[(tok0 + l) * (2 * DINNER) + DINNER + d];
        const float v = y * (r / (1.f + __expf(-r)));
        const __nv_bfloat16 hi = __float2bfloat16(v);
        yh[(tok0 + l) * DINNER + d] = hi;
        yl[(tok0 + l) * DINNER + d] = __float2bfloat16(v - __bfloat162float(hi));
    }
}

// ---------------- launch ----------------
extern "C" void kernel_launch(void* const* d_in, const int* in_sizes, int n_in,
                              void* d_out, int out_size) {
    const float* x      = (const float*)d_in[0];
    const float* rms_w  = (const float*)d_in[1];
    const float* W_in   = (const float*)d_in[2];
    const float* conv_w = (const float*)d_in[3];
    const float* conv_b = (const float*)d_in[4];
    const float* W_x    = (const float*)d_in[5];
    const float* W_dt   = (const float*)d_in[6];
    const float* A_log  = (const float*)d_in[7];
    const float* W_out  = (const float*)d_in[8];
    float* out = (float*)d_out;

    float *xr, *xs, *ssm, *dtb, *P, *Q, *H;
    __nv_bfloat16 *ah0, *al0, *ah1, *al1;
    __nv_bfloat16 *w1h, *w1l, *w2h, *w2l, *w3h, *w3l, *w4h, *w4l;
    cudaGetSymbolAddress((void**)&xr,  g_xr);
    cudaGetSymbolAddress((void**)&xs,  g_xs);
    cudaGetSymbolAddress((void**)&ssm, g_ssm);
    cudaGetSymbolAddress((void**)&dtb, g_dt);
    cudaGetSymbolAddress((void**)&P,   g_P);
    cudaGetSymbolAddress((void**)&Q,   g_Q);
    cudaGetSymbolAddress((void**)&H,   g_H);
    cudaGetSymbolAddress((void**)&ah0, g_ah0);  cudaGetSymbolAddress((void**)&al0, g_al0);
    cudaGetSymbolAddress((void**)&ah1, g_ah1);  cudaGetSymbolAddress((void**)&al1, g_al1);
    cudaGetSymbolAddress((void**)&w1h, g_w1h);  cudaGetSymbolAddress((void**)&w1l, g_w1l);
    cudaGetSymbolAddress((void**)&w2h, g_w2h);  cudaGetSymbolAddress((void**)&w2l, g_w2l);
    cudaGetSymbolAddress((void**)&w3h, g_w3h);  cudaGetSymbolAddress((void**)&w3l, g_w3l);
    cudaGetSymbolAddress((void**)&w4h, g_w4h);  cudaGetSymbolAddress((void**)&w4l, g_w4l);

    static bool attr_done = false;
    if (!attr_done) {
        cudaFuncSetAttribute(tcgemm_kernel<ACT_NONE, 0>,
            cudaFuncAttributeMaxDynamicSharedMemorySize, SMEM_TC);
        cudaFuncSetAttribute(tcgemm_kernel<ACT_NONE, 1>,
            cudaFuncAttributeMaxDynamicSharedMemorySize, SMEM_TC);
        cudaFuncSetAttribute(tcgemm_kernel<ACT_SOFTPLUS, 0>,
            cudaFuncAttributeMaxDynamicSharedMemorySize, SMEM_TC);
        cudaFuncSetAttribute(tcgemm_kernel<ACT_RESADD, 0>,
            cudaFuncAttributeMaxDynamicSharedMemorySize, SMEM_TC);
        attr_done = true;
    }

    const dim3 tb(32, 8);

    // weight split+transpose
    wsplit_t_kernel<<<dim3(4096 / 32, 1024 / 32), tb>>>(W_in,  w1h, w1l, 1024, 4096);
    wsplit_t_kernel<<<dim3(2176 / 32, 2048 / 32), tb>>>(W_x,   w2h, w2l, 2048, XW);
    wsplit_t_kernel<<<dim3(2048 / 32, 2048 / 32), tb>>>(W_dt,  w3h, w3l, 2048, 2048);
    wsplit_t_kernel<<<dim3(1024 / 32, 2048 / 32), tb>>>(W_out, w4h, w4l, 2048, 1024);

    // 1. RMSNorm -> split buf0
    rmsnorm_split_kernel<<<NTOK, 256>>>(x, rms_w, ah0, al0);

    // 2. xr = xn @ W_in   [2048,4096], K=1024
    tcgemm_kernel<ACT_NONE, 0><<<dim3(32, 16), 256, SMEM_TC>>>(
        ah0, al0, w1h, w1l, xr, nullptr, nullptr, nullptr, 4096, 1024, 4096, 0);

    // 3. conv + silu -> xs fp32 + split buf1
    conv_silu_kernel<<<(NTOK * DINNER / 2) / 256, 256>>>(xr, conv_w, conv_b,
                                                         xs, ah1, al1);

    // 4. x_ssm = xs @ W_x   [2048,2080], K=2048; epilogue splits dt-cols -> buf0
    tcgemm_kernel<ACT_NONE, 1><<<dim3(17, 16), 256, SMEM_TC>>>(
        ah1, al1, w2h, w2l, ssm, nullptr, ah0, al0, XW, 2048, XW, 0);

    // 5. dt = softplus(ssm[:, :2048] @ W_dt)   K=2048
    tcgemm_kernel<ACT_SOFTPLUS, 0><<<dim3(16, 16), 256, SMEM_TC>>>(
        ah0, al0, w3h, w3l, dtb, nullptr, nullptr, nullptr, 2048, 2048, 2048, 0);

    // 6. chunked parallel scan; p2 writes split yz -> buf1
    scan_p1<<<dim3(DINNER / 256, NSEG, BATCH), 256>>>(dtb, xs, ssm, A_log, P, Q);
    scan_combine<<<(BATCH * DSTATE * DINNER) / 256, 256>>>(P, Q, H);
    scan_p2<<<dim3(DINNER / 256, NSEG, BATCH), 256>>>(dtb, xs, ssm, xr, A_log, H,
                                                      ah1, al1);

    // 7. out = x + yz @ W_out   [2048,1024], K=2048
    tcgemm_kernel<ACT_RESADD, 0><<<dim3(8, 16), 256, SMEM_TC>>>(
        ah1, al1, w4h, w4l, out, x, nullptr, nullptr, 1024, 2048, 1024, 1024);
}

// round 9
// speedup vs baseline: 2.2548x; 1.0261x over previous
#include <cuda_runtime.h>
#include <cuda_bf16.h>
#include <math.h>
#include <stdint.h>

// ---------------- problem constants ----------------
#define BATCH    2
#define SEQ      1024
#define DMODEL   1024
#define DINNER   2048
#define DSTATE   16
#define NTOK     (BATCH * SEQ)          // 2048
#define XW       (DINNER + 2 * DSTATE)  // 2080
#define NSEG     32
#define GSEG     32

// ---------------- fp32 scratch ----------------
__device__ float g_xr [NTOK * 2 * DINNER];
__device__ float g_xs [NTOK * DINNER];
__device__ float g_ssm[NTOK * XW];
__device__ float g_dt [NTOK * DINNER];
__device__ float g_P  [BATCH * NSEG * DSTATE * DINNER];
__device__ float g_Q  [BATCH * NSEG * DSTATE * DINNER];
__device__ float g_H  [BATCH * NSEG * DSTATE * DINNER];

// ---------------- bf16 split buffers ----------------
__device__ __nv_bfloat16 g_ah0[NTOK * DINNER], g_al0[NTOK * DINNER];
__device__ __nv_bfloat16 g_ah1[NTOK * DINNER], g_al1[NTOK * DINNER];
__device__ __nv_bfloat16 g_w1h[4096 * 1024], g_w1l[4096 * 1024];   // W_in^T
__device__ __nv_bfloat16 g_w2h[2176 * 2048], g_w2l[2176 * 2048];   // W_x^T (padded)
__device__ __nv_bfloat16 g_w3h[2048 * 2048], g_w3l[2048 * 2048];   // W_dt^T
__device__ __nv_bfloat16 g_w4h[1024 * 2048], g_w4l[1024 * 2048];   // W_out^T

// ---------------- helpers ----------------
__device__ __forceinline__ uint32_t smem_u32(const void* p) {
    uint32_t a;
    asm("{ .reg .u64 t; cvta.to.shared.u64 t, %1; cvt.u32.u64 %0, t; }"
        : "=r"(a) : "l"(p));
    return a;
}
__device__ __forceinline__ void cp_async16s(uint32_t saddr, const void* gptr) {
    asm volatile("cp.async.cg.shared.global [%0], [%1], 16;\n"
                 :: "r"(saddr), "l"(gptr));
}
__device__ __forceinline__ void cp_commit() {
    asm volatile("cp.async.commit_group;\n");
}
__device__ __forceinline__ void ldsm4(uint32_t* r, uint32_t a) {
    asm volatile("ldmatrix.sync.aligned.m8n8.x4.shared.b16 {%0,%1,%2,%3}, [%4];"
                 : "=r"(r[0]), "=r"(r[1]), "=r"(r[2]), "=r"(r[3]) : "r"(a));
}
__device__ __forceinline__ void mma16816(float* c, const uint32_t* a,
                                         const uint32_t* b) {
    asm volatile(
        "mma.sync.aligned.m16n8k16.row.col.f32.bf16.bf16.f32 "
        "{%0,%1,%2,%3}, {%4,%5,%6,%7}, {%8,%9}, {%0,%1,%2,%3};"
        : "+f"(c[0]), "+f"(c[1]), "+f"(c[2]), "+f"(c[3])
        : "r"(a[0]), "r"(a[1]), "r"(a[2]), "r"(a[3]), "r"(b[0]), "r"(b[1]));
}
__device__ __forceinline__ void split2(__nv_bfloat16* h, __nv_bfloat16* l,
                                       float v0, float v1) {
    const __nv_bfloat16 h0 = __float2bfloat16(v0);
    const __nv_bfloat16 h1 = __float2bfloat16(v1);
    __nv_bfloat162 hh; hh.x = h0; hh.y = h1;
    __nv_bfloat162 ll;
    ll.x = __float2bfloat16(v0 - __bfloat162float(h0));
    ll.y = __float2bfloat16(v1 - __bfloat162float(h1));
    *reinterpret_cast<__nv_bfloat162*>(h) = hh;
    *reinterpret_cast<__nv_bfloat162*>(l) = ll;
}

// ---------------- RMSNorm, split output ----------------
__global__ void rmsnorm_split_kernel(const float* __restrict__ x,
                                     const float* __restrict__ w,
                                     __nv_bfloat16* __restrict__ oh,
                                     __nv_bfloat16* __restrict__ ol) {
    const int t   = blockIdx.x;
    const int tid = threadIdx.x;
    const float4 v = reinterpret_cast<const float4*>(x + t * DMODEL)[tid];
    float s = v.x * v.x + v.y * v.y + v.z * v.z + v.w * v.w;
    #pragma unroll
    for (int o = 16; o; o >>= 1) s += __shfl_xor_sync(0xffffffffu, s, o);
    __shared__ float red[8];
    __shared__ float sscale;
    if ((tid & 31) == 0) red[tid >> 5] = s;
    __syncthreads();
    if (tid == 0) {
        float tot = 0.f;
        #pragma unroll
        for (int i = 0; i < 8; ++i) tot += red[i];
        sscale = rsqrtf(tot * (1.0f / DMODEL) + 1e-5f);
    }
    __syncthreads();
    const float sc = sscale;
    const float4 wv = reinterpret_cast<const float4*>(w)[tid];
    const int base = t * DMODEL + tid * 4;
    split2(&oh[base],     &ol[base],     v.x * sc * wv.x, v.y * sc * wv.y);
    split2(&oh[base + 2], &ol[base + 2], v.z * sc * wv.z, v.w * sc * wv.w);
}

// ---------------- depthwise causal conv + SiLU ----------------
__global__ void conv_silu_kernel(const float* __restrict__ xr,
                                 const float* __restrict__ cw,
                                 const float* __restrict__ cb,
                                 float* __restrict__ xs,
                                 __nv_bfloat16* __restrict__ oh,
                                 __nv_bfloat16* __restrict__ ol) {
    const int idx = (blockIdx.x * blockDim.x + threadIdx.x) * 2;
    const int d   = idx & (DINNER - 1);
    const int tok = idx >> 11;
    const int l   = tok & (SEQ - 1);
    float a0 = cb[d], a1 = cb[d + 1];
    #pragma unroll
    for (int j = 0; j < 4; ++j) {
        const int ls = l - 3 + j;
        if (ls >= 0) {
            const float2 xv = *reinterpret_cast<const float2*>(
                &xr[(tok + j - 3) * (2 * DINNER) + d]);
            a0 = fmaf(cw[d * 4 + j],       xv.x, a0);
            a1 = fmaf(cw[(d + 1) * 4 + j], xv.y, a1);
        }
    }
    a0 = a0 / (1.f + __expf(-a0));
    a1 = a1 / (1.f + __expf(-a1));
    *reinterpret_cast<float2*>(&xs[idx]) = make_float2(a0, a1);
    split2(&oh[idx], &ol[idx], a0, a1);
}

// ---------------- merged weight split+transpose (all 4 weights, 1 launch) ---
// segs: [0,4096) W_in | [4096,8448) W_x | [8448,12544) W_dt | [12544,14592) W_out
__global__ void wsplit_all_kernel(const float* __restrict__ W1,
                                  const float* __restrict__ W2,
                                  const float* __restrict__ W3,
                                  const float* __restrict__ W4,
                                  __nv_bfloat16* __restrict__ w1h, __nv_bfloat16* __restrict__ w1l,
                                  __nv_bfloat16* __restrict__ w2h, __nv_bfloat16* __restrict__ w2l,
                                  __nv_bfloat16* __restrict__ w3h, __nv_bfloat16* __restrict__ w3l,
                                  __nv_bfloat16* __restrict__ w4h, __nv_bfloat16* __restrict__ w4l) {
    const int id = blockIdx.x;
    const float* W; __nv_bfloat16 *Th, *Tl;
    int K, N, nbn, rel;
    if (id < 4096)       { W = W1; Th = w1h; Tl = w1l; K = 1024; N = 4096; nbn = 128; rel = id; }
    else if (id < 8448)  { W = W2; Th = w2h; Tl = w2l; K = 2048; N = XW;   nbn = 68;  rel = id - 4096; }
    else if (id < 12544) { W = W3; Th = w3h; Tl = w3l; K = 2048; N = 2048; nbn = 64;  rel = id - 8448; }
    else                 { W = W4; Th = w4h; Tl = w4l; K = 2048; N = 1024; nbn = 32;  rel = id - 12544; }
    const int n0 = (rel % nbn) * 32, k0 = (rel / nbn) * 32;

    __shared__ float tile[32][33];
    const int tx = threadIdx.x, ty = threadIdx.y;   // 32 x 8
    #pragma unroll
    for (int r = 0; r < 4; ++r) {
        const int k = k0 + ty + 8 * r, n = n0 + tx;
        tile[ty + 8 * r][tx] = (n < N) ? W[(size_t)k * N + n] : 0.f;
    }
    __syncthreads();
    #pragma unroll
    for (int r = 0; r < 4; ++r) {
        const int nrow = n0 + ty + 8 * r, k = k0 + tx;
        const float v = tile[tx][ty + 8 * r];
        const __nv_bfloat16 hi = __float2bfloat16(v);
        Th[(size_t)nrow * K + k] = hi;
        Tl[(size_t)nrow * K + k] = __float2bfloat16(v - __bfloat162float(hi));
    }
}

// ---------------- mma.sync bf16-split GEMM (templated BM) ----------------
// smem stage: Ah(BM*64) | Al(BM*64) | Bh(8192) | Bl(8192)
#define TCK 32

#define ACT_NONE     0
#define ACT_SOFTPLUS 1
#define ACT_RESADD   2

template <int ACT, int SPLIT, int BM>
__global__ __launch_bounds__(256, 2)
void tcgemm_kernel(const __nv_bfloat16* __restrict__ Ah,
                   const __nv_bfloat16* __restrict__ Al,
                   const __nv_bfloat16* __restrict__ Bh,
                   const __nv_bfloat16* __restrict__ Bl,
                   float* __restrict__ D, const float* __restrict__ Res,
                   __nv_bfloat16* __restrict__ Sh, __nv_bfloat16* __restrict__ Sl,
                   int N, int K, int ldd, int ldr) {
    constexpr int TM    = BM / 32;        // m16 tiles per warp
    constexpr int ALOFF = BM * 64;
    constexpr int BOFF  = 2 * BM * 64;
    constexpr int STAGE = BM * 128 + 16384;

    extern __shared__ unsigned char sm[];
    const uint32_t smb = smem_u32(sm);

    const int tid  = threadIdx.x;
    const int lane = tid & 31;
    const int wid  = tid >> 5;
    const int wm   = wid >> 2;
    const int wn   = wid & 3;
    const int m0   = blockIdx.y * BM;
    const int n0   = blockIdx.x * 128;

    // ---- cp.async geometry: B part (128 rows, 2 granules/thread/matrix)
    const int lrowB = tid >> 1;
    const int gpB   = (tid & 1) * 2;
    const int swB   = (lrowB >> 1) & 3;
    const uint32_t dstB0 = BOFF + lrowB * 64 + (((gpB + 0) ^ swB) << 4);
    const uint32_t dstB1 = BOFF + lrowB * 64 + (((gpB + 1) ^ swB) << 4);
    const __nv_bfloat16* srcBh = Bh + (size_t)(n0 + lrowB) * K + gpB * 8;
    const __nv_bfloat16* srcBl = Bl + (size_t)(n0 + lrowB) * K + gpB * 8;

    // ---- A part
    uint32_t dstA0, dstA1 = 0;
    const __nv_bfloat16 *srcAh, *srcAl;
    if constexpr (BM == 128) {
        dstA0 = lrowB * 64 + (((gpB + 0) ^ swB) << 4);
        dstA1 = lrowB * 64 + (((gpB + 1) ^ swB) << 4);
        srcAh = Ah + (size_t)(m0 + lrowB) * K + gpB * 8;
        srcAl = Al + (size_t)(m0 + lrowB) * K + gpB * 8;
    } else {
        const int lrowA = tid >> 2;
        const int gpA   = tid & 3;
        dstA0 = lrowA * 64 + ((gpA ^ ((lrowA >> 1) & 3)) << 4);
        srcAh = Ah + (size_t)(m0 + lrowA) * K + gpA * 8;
        srcAl = Al + (size_t)(m0 + lrowA) * K + gpA * 8;
    }

    // ---- ldmatrix geometry
    const int agsel = lane >> 4;
    const int rowA  = wm * (BM / 2) + (lane & 15);
    const uint32_t offA = rowA * 64 + ((agsel ^ ((rowA >> 1) & 3)) << 4);
    const int nr    = (lane & 7) + ((lane >> 4) << 3);
    const int kgsel = (lane >> 3) & 1;
    const int rowB  = wn * 32 + nr;
    const uint32_t offB = BOFF + rowB * 64 + ((kgsel ^ ((rowB >> 1) & 3)) << 4);

    const int T = K / TCK;

    auto load_chunk = [&](int stage, int k0) {
        const uint32_t sb_ = smb + stage * STAGE;
        if constexpr (BM == 128) {
            cp_async16s(sb_ + dstA0,         srcAh + k0);
            cp_async16s(sb_ + dstA1,         srcAh + k0 + 8);
            cp_async16s(sb_ + ALOFF + dstA0, srcAl + k0);
            cp_async16s(sb_ + ALOFF + dstA1, srcAl + k0 + 8);
        } else {
            cp_async16s(sb_ + dstA0,         srcAh + k0);
            cp_async16s(sb_ + ALOFF + dstA0, srcAl + k0);
        }
        cp_async16s(sb_ + dstB0,        srcBh + k0);
        cp_async16s(sb_ + dstB1,        srcBh + k0 + 8);
        cp_async16s(sb_ + 8192 + dstB0, srcBl + k0);
        cp_async16s(sb_ + 8192 + dstB1, srcBl + k0 + 8);
        cp_commit();
    };

    load_chunk(0, 0);
    load_chunk(1, TCK);

    float acc[TM][4][4];
    #pragma unroll
    for (int t = 0; t < TM; ++t)
        #pragma unroll
        for (int j = 0; j < 4; ++j)
            #pragma unroll
            for (int q = 0; q < 4; ++q) acc[t][j][q] = 0.f;

    for (int i = 0; i < T; ++i) {
        asm volatile("cp.async.wait_group 1;\n" ::: "memory");
        __syncthreads();

        if (i + 2 < T) load_chunk((i + 2) % 3, (i + 2) * TCK);
        else           cp_commit();

        const uint32_t sb = smb + (i % 3) * STAGE;
        #pragma unroll
        for (int ks = 0; ks < 2; ++ks) {
            const uint32_t kx = ks * 32;
            uint32_t ah_[TM][4], al_[TM][4];
            #pragma unroll
            for (int t = 0; t < TM; ++t) {
                const uint32_t oa = (offA + t * 1024) ^ kx;
                ldsm4(ah_[t], sb + oa);
                ldsm4(al_[t], sb + ALOFF + oa);
            }
            #pragma unroll
            for (int p = 0; p < 2; ++p) {
                uint32_t bh_[4], bl_[4];
                const uint32_t ob = (offB + p * 1024) ^ kx;
                ldsm4(bh_, sb + ob);
                ldsm4(bl_, sb + ob + 8192);
                #pragma unroll
                for (int t = 0; t < TM; ++t) {
                    mma16816(acc[t][2 * p],     ah_[t], bh_);
                    mma16816(acc[t][2 * p + 1], ah_[t], bh_ + 2);
                    mma16816(acc[t][2 * p],     al_[t], bh_);
                    mma16816(acc[t][2 * p + 1], al_[t], bh_ + 2);
                    mma16816(acc[t][2 * p],     ah_[t], bl_);
                    mma16816(acc[t][2 * p + 1], ah_[t], bl_ + 2);
                }
            }
        }
    }

    // ---- epilogue
    const int g  = lane >> 2;
    const int tg = lane & 3;
    #pragma unroll
    for (int t = 0; t < TM; ++t) {
        const int row = m0 + wm * (BM / 2) + t * 16 + g;
        #pragma unroll
        for (int j = 0; j < 4; ++j) {
            const int col = n0 + wn * 32 + j * 8 + 2 * tg;
            if (col < N) {
                float c0 = acc[t][j][0], c1 = acc[t][j][1];
                float c2 = acc[t][j][2], c3 = acc[t][j][3];
                if (ACT == ACT_SOFTPLUS) {
                    c0 = fmaxf(c0, 0.f) + log1pf(__expf(-fabsf(c0)));
                    c1 = fmaxf(c1, 0.f) + log1pf(__expf(-fabsf(c1)));
                    c2 = fmaxf(c2, 0.f) + log1pf(__expf(-fabsf(c2)));
                    c3 = fmaxf(c3, 0.f) + log1pf(__expf(-fabsf(c3)));
                }
                if (ACT == ACT_RESADD) {
                    const float2 r0 = *reinterpret_cast<const float2*>(
                        &Res[(size_t)row * ldr + col]);
                    const float2 r1 = *reinterpret_cast<const float2*>(
                        &Res[(size_t)(row + 8) * ldr + col]);
                    c0 += r0.x; c1 += r0.y; c2 += r1.x; c3 += r1.y;
                }
                // SPLIT mode: dt-cols (<DINNER) go ONLY to split bufs; fp32
                // stores only for the B/C columns the scan actually reads.
                const bool storef = SPLIT ? (col >= DINNER) : true;
                if (storef) {
                    *reinterpret_cast<float2*>(&D[(size_t)row * ldd + col]) =
                        make_float2(c0, c1);
                    *reinterpret_cast<float2*>(&D[(size_t)(row + 8) * ldd + col]) =
                        make_float2(c2, c3);
                }
                if (SPLIT && col < DINNER) {
                    split2(&Sh[(size_t)row * DINNER + col],
                           &Sl[(size_t)row * DINNER + col], c0, c1);
                    split2(&Sh[(size_t)(row + 8) * DINNER + col],
                           &Sl[(size_t)(row + 8) * DINNER + col], c2, c3);
                }
            }
        }
    }
}

// ---------------- chunked parallel selective scan ----------------
__global__ __launch_bounds__(256)
void scan_p1(const float* __restrict__ dt, const float* __restrict__ xs,
             const float* __restrict__ ssm, const float* __restrict__ A_log,
             float* __restrict__ P, float* __restrict__ Q) {
    __shared__ float Bsh[GSEG][DSTATE];
    const int b = blockIdx.z, s = blockIdx.y;
    const int d = blockIdx.x * 256 + threadIdx.x;
    const int tok0 = b * SEQ + s * GSEG;

    for (int v = threadIdx.x; v < GSEG * DSTATE; v += 256) {
        const int l = v >> 4, n = v & 15;
        Bsh[l][n] = ssm[(tok0 + l) * XW + DINNER + n];
    }
    __syncthreads();

    float Ac[DSTATE];
    #pragma unroll
    for (int q = 0; q < 4; ++q) {
        const float4 v = reinterpret_cast<const float4*>(&A_log[d * DSTATE])[q];
        Ac[4 * q + 0] = -__expf(v.x);  Ac[4 * q + 1] = -__expf(v.y);
        Ac[4 * q + 2] = -__expf(v.z);  Ac[4 * q + 3] = -__expf(v.w);
    }

    float h[DSTATE];
    #pragma unroll
    for (int n = 0; n < DSTATE; ++n) h[n] = 0.f;
    float sdt = 0.f;

    for (int l = 0; l < GSEG; ++l) {
        const float dtv = dt[(tok0 + l) * DINNER + d];
        const float xv  = xs[(tok0 + l) * DINNER + d];
        sdt += dtv;
        const float dtx = dtv * xv;
        #pragma unroll
        for (int n = 0; n < DSTATE; ++n)
            h[n] = fmaf(__expf(Ac[n] * dtv), h[n], dtx * Bsh[l][n]);
    }

    const int basei = ((b * NSEG + s) * DSTATE) * DINNER + d;
    #pragma unroll
    for (int n = 0; n < DSTATE; ++n) {
        P[basei + n * DINNER] = __expf(Ac[n] * sdt);
        Q[basei + n * DINNER] = h[n];
    }
}

__global__ void scan_combine(const float* __restrict__ P,
                             const float* __restrict__ Q,
                             float* __restrict__ H) {
    const int t = blockIdx.x * 256 + threadIdx.x;
    const int d = t & (DINNER - 1);
    const int n = (t >> 11) & 15;
    const int b = t >> 15;
    float h = 0.f;
    for (int s = 0; s < NSEG; ++s) {
        const int off = ((b * NSEG + s) * DSTATE + n) * DINNER + d;
        H[off] = h;
        h = fmaf(P[off], h, Q[off]);
    }
}

__global__ __launch_bounds__(256)
void scan_p2(const float* __restrict__ dt, const float* __restrict__ xs,
             const float* __restrict__ ssm, const float* __restrict__ xr,
             const float* __restrict__ A_log, const float* __restrict__ H,
             __nv_bfloat16* __restrict__ yh, __nv_bfloat16* __restrict__ yl) {
    __shared__ float Bsh[GSEG][DSTATE];
    __shared__ float Csh[GSEG][DSTATE];
    const int b = blockIdx.z, s = blockIdx.y;
    const int d = blockIdx.x * 256 + threadIdx.x;
    const int tok0 = b * SEQ + s * GSEG;

    for (int v = threadIdx.x; v < GSEG * DSTATE * 2; v += 256) {
        const int l = v >> 5, j = v & 31;
        const float val = ssm[(tok0 + l) * XW + DINNER + j];
        if (j < DSTATE) Bsh[l][j] = val;
        else            Csh[l][j - DSTATE] = val;
    }
    __syncthreads();

    float Ac[DSTATE];
    #pragma unroll
    for (int q = 0; q < 4; ++q) {
        const float4 v = reinterpret_cast<const float4*>(&A_log[d * DSTATE])[q];
        Ac[4 * q + 0] = -__expf(v.x);  Ac[4 * q + 1] = -__expf(v.y);
        Ac[4 * q + 2] = -__expf(v.z);  Ac[4 * q + 3] = -__expf(v.w);
    }

    const int basei = ((b * NSEG + s) * DSTATE) * DINNER + d;
    float h[DSTATE];
    #pragma unroll
    for (int n = 0; n < DSTATE; ++n) h[n] = H[basei + n * DINNER];

    for (int l = 0; l < GSEG; ++l) {
        const float dtv = dt[(tok0 + l) * DINNER + d];
        const float xv  = xs[(tok0 + l) * DINNER + d];
        const float dtx = dtv * xv;
        float y = 0.f;
        #pragma unroll
        for (int n = 0; n < DSTATE; ++n) {
            h[n] = fmaf(__expf(Ac[n] * dtv), h[n], dtx * Bsh[l][n]);
            y = fmaf(h[n], Csh[l][n], y);
        }
        const float r = xr[(tok0 + l) * (2 * DINNER) + DINNER + d];
        const float v = y * (r / (1.f + __expf(-r)));
        const __nv_bfloat16 hi = __float2bfloat16(v);
        yh[(tok0 + l) * DINNER + d] = hi;
        yl[(tok0 + l) * DINNER + d] = __float2bfloat16(v - __bfloat162float(hi));
    }
}

// ---------------- launch ----------------
extern "C" void kernel_launch(void* const* d_in, const int* in_sizes, int n_in,
                              void* d_out, int out_size) {
    const float* x      = (const float*)d_in[0];
    const float* rms_w  = (const float*)d_in[1];
    const float* W_in   = (const float*)d_in[2];
    const float* conv_w = (const float*)d_in[3];
    const float* conv_b = (const float*)d_in[4];
    const float* W_x    = (const float*)d_in[5];
    const float* W_dt   = (const float*)d_in[6];
    const float* A_log  = (const float*)d_in[7];
    const float* W_out  = (const float*)d_in[8];
    float* out = (float*)d_out;

    float *xr, *xs, *ssm, *dtb, *P, *Q, *H;
    __nv_bfloat16 *ah0, *al0, *ah1, *al1;
    __nv_bfloat16 *w1h, *w1l, *w2h, *w2l, *w3h, *w3l, *w4h, *w4l;
    cudaGetSymbolAddress((void**)&xr,  g_xr);
    cudaGetSymbolAddress((void**)&xs,  g_xs);
    cudaGetSymbolAddress((void**)&ssm, g_ssm);
    cudaGetSymbolAddress((void**)&dtb, g_dt);
    cudaGetSymbolAddress((void**)&P,   g_P);
    cudaGetSymbolAddress((void**)&Q,   g_Q);
    cudaGetSymbolAddress((void**)&H,   g_H);
    cudaGetSymbolAddress((void**)&ah0, g_ah0);  cudaGetSymbolAddress((void**)&al0, g_al0);
    cudaGetSymbolAddress((void**)&ah1, g_ah1);  cudaGetSymbolAddress((void**)&al1, g_al1);
    cudaGetSymbolAddress((void**)&w1h, g_w1h);  cudaGetSymbolAddress((void**)&w1l, g_w1l);
    cudaGetSymbolAddress((void**)&w2h, g_w2h);  cudaGetSymbolAddress((void**)&w2l, g_w2l);
    cudaGetSymbolAddress((void**)&w3h, g_w3h);  cudaGetSymbolAddress((void**)&w3l, g_w3l);
    cudaGetSymbolAddress((void**)&w4h, g_w4h);  cudaGetSymbolAddress((void**)&w4l, g_w4l);

    constexpr int SM128 = 3 * (128 * 128 + 16384);   // 98304
    constexpr int SM64  = 3 * (64 * 128 + 16384);    // 73728

    static bool attr_done = false;
    if (!attr_done) {
        cudaFuncSetAttribute(tcgemm_kernel<ACT_NONE, 0, 128>,
            cudaFuncAttributeMaxDynamicSharedMemorySize, SM128);
        cudaFuncSetAttribute(tcgemm_kernel<ACT_NONE, 1, 128>,
            cudaFuncAttributeMaxDynamicSharedMemorySize, SM128);
        cudaFuncSetAttribute(tcgemm_kernel<ACT_SOFTPLUS, 0, 128>,
            cudaFuncAttributeMaxDynamicSharedMemorySize, SM128);
        cudaFuncSetAttribute(tcgemm_kernel<ACT_RESADD, 0, 64>,
            cudaFuncAttributeMaxDynamicSharedMemorySize, SM64);
        attr_done = true;
    }

    // weight split+transpose, single launch
    wsplit_all_kernel<<<14592, dim3(32, 8)>>>(W_in, W_x, W_dt, W_out,
        w1h, w1l, w2h, w2l, w3h, w3l, w4h, w4l);

    // 1. RMSNorm -> split buf0
    rmsnorm_split_kernel<<<NTOK, 256>>>(x, rms_w, ah0, al0);

    // 2. xr = xn @ W_in   [2048,4096], K=1024
    tcgemm_kernel<ACT_NONE, 0, 128><<<dim3(32, 16), 256, SM128>>>(
        ah0, al0, w1h, w1l, xr, nullptr, nullptr, nullptr, 4096, 1024, 4096, 0);

    // 3. conv + silu -> xs fp32 + split buf1
    conv_silu_kernel<<<(NTOK * DINNER / 2) / 256, 256>>>(xr, conv_w, conv_b,
                                                         xs, ah1, al1);

    // 4. x_ssm = xs @ W_x   [2048,2080], K=2048; dt-cols split -> buf0
    tcgemm_kernel<ACT_NONE, 1, 128><<<dim3(17, 16), 256, SM128>>>(
        ah1, al1, w2h, w2l, ssm, nullptr, ah0, al0, XW, 2048, XW, 0);

    // 5. dt = softplus(ssm_dt @ W_dt)   K=2048
    tcgemm_kernel<ACT_SOFTPLUS, 0, 128><<<dim3(16, 16), 256, SM128>>>(
        ah0, al0, w3h, w3l, dtb, nullptr, nullptr, nullptr, 2048, 2048, 2048, 0);

    // 6. chunked parallel scan; p2 writes split yz -> buf1
    scan_p1<<<dim3(DINNER / 256, NSEG, BATCH), 256>>>(dtb, xs, ssm, A_log, P, Q);
    scan_combine<<<(BATCH * DSTATE * DINNER) / 256, 256>>>(P, Q, H);
    scan_p2<<<dim3(DINNER / 256, NSEG, BATCH), 256>>>(dtb, xs, ssm, xr, A_log, H,
                                                      ah1, al1);

    // 7. out = x + yz @ W_out   [2048,1024], K=2048  (BM=64 -> 256 CTAs)
    tcgemm_kernel<ACT_RESADD, 0, 64><<<dim3(8, 32), 256, SM64>>>(
        ah1, al1, w4h, w4l, out, x, nullptr, nullptr, 1024, 2048, 1024, 1024);
}

// round 10
// speedup vs baseline: 2.2671x; 1.0054x over previous
#include <cuda_runtime.h>
#include <cuda_bf16.h>
#include <math.h>
#include <stdint.h>

// ---------------- problem constants ----------------
#define BATCH    2
#define SEQ      1024
#define DMODEL   1024
#define DINNER   2048
#define DSTATE   16
#define NTOK     (BATCH * SEQ)          // 2048
#define XW       (DINNER + 2 * DSTATE)  // 2080
#define NSEG     32
#define GSEG     32

// ---------------- fp32 scratch ----------------
__device__ float g_xr [NTOK * 2 * DINNER];
__device__ float g_xs [NTOK * DINNER];
__device__ float g_ssm[NTOK * XW];
__device__ float g_dt [NTOK * DINNER];
__device__ float g_P  [BATCH * NSEG * DSTATE * DINNER];
__device__ float g_Q  [BATCH * NSEG * DSTATE * DINNER];
__device__ float g_H  [BATCH * NSEG * DSTATE * DINNER];

// ---------------- bf16 split buffers ----------------
__device__ __nv_bfloat16 g_ah0[NTOK * DINNER], g_al0[NTOK * DINNER];
__device__ __nv_bfloat16 g_ah1[NTOK * DINNER], g_al1[NTOK * DINNER];
__device__ __nv_bfloat16 g_w1h[4096 * 1024], g_w1l[4096 * 1024];   // W_in^T
__device__ __nv_bfloat16 g_w2h[2176 * 2048], g_w2l[2176 * 2048];   // W_x^T (padded)
__device__ __nv_bfloat16 g_w3h[2048 * 2048], g_w3l[2048 * 2048];   // W_dt^T
__device__ __nv_bfloat16 g_w4h[1024 * 2048], g_w4l[1024 * 2048];   // W_out^T

// ---------------- helpers ----------------
__device__ __forceinline__ uint32_t smem_u32(const void* p) {
    uint32_t a;
    asm("{ .reg .u64 t; cvta.to.shared.u64 t, %1; cvt.u32.u64 %0, t; }"
        : "=r"(a) : "l"(p));
    return a;
}
__device__ __forceinline__ void cp_async16s(uint32_t saddr, const void* gptr) {
    asm volatile("cp.async.cg.shared.global [%0], [%1], 16;\n"
                 :: "r"(saddr), "l"(gptr));
}
__device__ __forceinline__ void cp_commit() {
    asm volatile("cp.async.commit_group;\n");
}
__device__ __forceinline__ void ldsm4(uint32_t* r, uint32_t a) {
    asm volatile("ldmatrix.sync.aligned.m8n8.x4.shared.b16 {%0,%1,%2,%3}, [%4];"
                 : "=r"(r[0]), "=r"(r[1]), "=r"(r[2]), "=r"(r[3]) : "r"(a));
}
__device__ __forceinline__ void mma16816(float* c, const uint32_t* a,
                                         const uint32_t* b) {
    asm volatile(
        "mma.sync.aligned.m16n8k16.row.col.f32.bf16.bf16.f32 "
        "{%0,%1,%2,%3}, {%4,%5,%6,%7}, {%8,%9}, {%0,%1,%2,%3};"
        : "+f"(c[0]), "+f"(c[1]), "+f"(c[2]), "+f"(c[3])
        : "r"(a[0]), "r"(a[1]), "r"(a[2]), "r"(a[3]), "r"(b[0]), "r"(b[1]));
}
__device__ __forceinline__ void split2(__nv_bfloat16* h, __nv_bfloat16* l,
                                       float v0, float v1) {
    const __nv_bfloat16 h0 = __float2bfloat16(v0);
    const __nv_bfloat16 h1 = __float2bfloat16(v1);
    __nv_bfloat162 hh; hh.x = h0; hh.y = h1;
    __nv_bfloat162 ll;
    ll.x = __float2bfloat16(v0 - __bfloat162float(h0));
    ll.y = __float2bfloat16(v1 - __bfloat162float(h1));
    *reinterpret_cast<__nv_bfloat162*>(h) = hh;
    *reinterpret_cast<__nv_bfloat162*>(l) = ll;
}
__device__ __forceinline__ float fast_silu(float a) {
    return __fdividef(a, 1.f + __expf(-a));
}

// ---------------- RMSNorm, split output ----------------
__global__ void rmsnorm_split_kernel(const float* __restrict__ x,
                                     const float* __restrict__ w,
                                     __nv_bfloat16* __restrict__ oh,
                                     __nv_bfloat16* __restrict__ ol) {
    const int t   = blockIdx.x;
    const int tid = threadIdx.x;
    const float4 v = reinterpret_cast<const float4*>(x + t * DMODEL)[tid];
    float s = v.x * v.x + v.y * v.y + v.z * v.z + v.w * v.w;
    #pragma unroll
    for (int o = 16; o; o >>= 1) s += __shfl_xor_sync(0xffffffffu, s, o);
    __shared__ float red[8];
    __shared__ float sscale;
    if ((tid & 31) == 0) red[tid >> 5] = s;
    __syncthreads();
    if (tid == 0) {
        float tot = 0.f;
        #pragma unroll
        for (int i = 0; i < 8; ++i) tot += red[i];
        sscale = rsqrtf(tot * (1.0f / DMODEL) + 1e-5f);
    }
    __syncthreads();
    const float sc = sscale;
    const float4 wv = reinterpret_cast<const float4*>(w)[tid];
    const int base = t * DMODEL + tid * 4;
    split2(&oh[base],     &ol[base],     v.x * sc * wv.x, v.y * sc * wv.y);
    split2(&oh[base + 2], &ol[base + 2], v.z * sc * wv.z, v.w * sc * wv.w);
}

// ---------------- depthwise causal conv + SiLU (float4/thread) ----------------
__global__ void conv_silu_kernel(const float* __restrict__ xr,
                                 const float* __restrict__ cw,
                                 const float* __restrict__ cb,
                                 float* __restrict__ xs,
                                 __nv_bfloat16* __restrict__ oh,
                                 __nv_bfloat16* __restrict__ ol) {
    const int idx = (blockIdx.x * blockDim.x + threadIdx.x) * 4;
    const int d   = idx & (DINNER - 1);
    const int tok = idx >> 11;
    const int l   = tok & (SEQ - 1);
    const float4* cw4 = reinterpret_cast<const float4*>(cw);
    const float4 w0 = cw4[d];
    const float4 w1 = cw4[d + 1];
    const float4 w2 = cw4[d + 2];
    const float4 w3 = cw4[d + 3];
    float4 a = reinterpret_cast<const float4*>(cb)[d >> 2];
    #pragma unroll
    for (int j = 0; j < 4; ++j) {
        const int ls = l - 3 + j;
        if (ls >= 0) {
            const float4 xv = *reinterpret_cast<const float4*>(
                &xr[(tok + j - 3) * (2 * DINNER) + d]);
            const float t0 = (j == 0) ? w0.x : (j == 1) ? w0.y : (j == 2) ? w0.z : w0.w;
            const float t1 = (j == 0) ? w1.x : (j == 1) ? w1.y : (j == 2) ? w1.z : w1.w;
            const float t2 = (j == 0) ? w2.x : (j == 1) ? w2.y : (j == 2) ? w2.z : w2.w;
            const float t3 = (j == 0) ? w3.x : (j == 1) ? w3.y : (j == 2) ? w3.z : w3.w;
            a.x = fmaf(t0, xv.x, a.x);
            a.y = fmaf(t1, xv.y, a.y);
            a.z = fmaf(t2, xv.z, a.z);
            a.w = fmaf(t3, xv.w, a.w);
        }
    }
    a.x = fast_silu(a.x);  a.y = fast_silu(a.y);
    a.z = fast_silu(a.z);  a.w = fast_silu(a.w);
    *reinterpret_cast<float4*>(&xs[idx]) = a;
    split2(&oh[idx],     &ol[idx],     a.x, a.y);
    split2(&oh[idx + 2], &ol[idx + 2], a.z, a.w);
}

// ---------------- merged weight split+transpose ----------------
__global__ void wsplit_all_kernel(const float* __restrict__ W1,
                                  const float* __restrict__ W2,
                                  const float* __restrict__ W3,
                                  const float* __restrict__ W4,
                                  __nv_bfloat16* __restrict__ w1h, __nv_bfloat16* __restrict__ w1l,
                                  __nv_bfloat16* __restrict__ w2h, __nv_bfloat16* __restrict__ w2l,
                                  __nv_bfloat16* __restrict__ w3h, __nv_bfloat16* __restrict__ w3l,
                                  __nv_bfloat16* __restrict__ w4h, __nv_bfloat16* __restrict__ w4l) {
    const int id = blockIdx.x;
    const float* W; __nv_bfloat16 *Th, *Tl;
    int K, N, nbn, rel;
    if (id < 4096)       { W = W1; Th = w1h; Tl = w1l; K = 1024; N = 4096; nbn = 128; rel = id; }
    else if (id < 8448)  { W = W2; Th = w2h; Tl = w2l; K = 2048; N = XW;   nbn = 68;  rel = id - 4096; }
    else if (id < 12544) { W = W3; Th = w3h; Tl = w3l; K = 2048; N = 2048; nbn = 64;  rel = id - 8448; }
    else                 { W = W4; Th = w4h; Tl = w4l; K = 2048; N = 1024; nbn = 32;  rel = id - 12544; }
    const int n0 = (rel % nbn) * 32, k0 = (rel / nbn) * 32;

    __shared__ float tile[32][33];
    const int tx = threadIdx.x, ty = threadIdx.y;   // 32 x 8
    #pragma unroll
    for (int r = 0; r < 4; ++r) {
        const int k = k0 + ty + 8 * r, n = n0 + tx;
        tile[ty + 8 * r][tx] = (n < N) ? W[(size_t)k * N + n] : 0.f;
    }
    __syncthreads();
    #pragma unroll
    for (int r = 0; r < 4; ++r) {
        const int nrow = n0 + ty + 8 * r, k = k0 + tx;
        const float v = tile[tx][ty + 8 * r];
        const __nv_bfloat16 hi = __float2bfloat16(v);
        Th[(size_t)nrow * K + k] = hi;
        Tl[(size_t)nrow * K + k] = __float2bfloat16(v - __bfloat162float(hi));
    }
}

// ---------------- mma.sync bf16-split GEMM (templated BM) ----------------
#define TCK 32

#define ACT_NONE     0
#define ACT_SOFTPLUS 1
#define ACT_RESADD   2

template <int ACT, int SPLIT, int BM>
__global__ __launch_bounds__(256, 2)
void tcgemm_kernel(const __nv_bfloat16* __restrict__ Ah,
                   const __nv_bfloat16* __restrict__ Al,
                   const __nv_bfloat16* __restrict__ Bh,
                   const __nv_bfloat16* __restrict__ Bl,
                   float* __restrict__ D, const float* __restrict__ Res,
                   __nv_bfloat16* __restrict__ Sh, __nv_bfloat16* __restrict__ Sl,
                   int N, int K, int ldd, int ldr) {
    constexpr int TM    = BM / 32;
    constexpr int ALOFF = BM * 64;
    constexpr int BOFF  = 2 * BM * 64;
    constexpr int STAGE = BM * 128 + 16384;

    extern __shared__ unsigned char sm[];
    const uint32_t smb = smem_u32(sm);

    const int tid  = threadIdx.x;
    const int lane = tid & 31;
    const int wid  = tid >> 5;
    const int wm   = wid >> 2;
    const int wn   = wid & 3;
    const int m0   = blockIdx.y * BM;
    const int n0   = blockIdx.x * 128;

    const int lrowB = tid >> 1;
    const int gpB   = (tid & 1) * 2;
    const int swB   = (lrowB >> 1) & 3;
    const uint32_t dstB0 = BOFF + lrowB * 64 + (((gpB + 0) ^ swB) << 4);
    const uint32_t dstB1 = BOFF + lrowB * 64 + (((gpB + 1) ^ swB) << 4);
    const __nv_bfloat16* srcBh = Bh + (size_t)(n0 + lrowB) * K + gpB * 8;
    const __nv_bfloat16* srcBl = Bl + (size_t)(n0 + lrowB) * K + gpB * 8;

    uint32_t dstA0, dstA1 = 0;
    const __nv_bfloat16 *srcAh, *srcAl;
    if constexpr (BM == 128) {
        dstA0 = lrowB * 64 + (((gpB + 0) ^ swB) << 4);
        dstA1 = lrowB * 64 + (((gpB + 1) ^ swB) << 4);
        srcAh = Ah + (size_t)(m0 + lrowB) * K + gpB * 8;
        srcAl = Al + (size_t)(m0 + lrowB) * K + gpB * 8;
    } else {
        const int lrowA = tid >> 2;
        const int gpA   = tid & 3;
        dstA0 = lrowA * 64 + ((gpA ^ ((lrowA >> 1) & 3)) << 4);
        srcAh = Ah + (size_t)(m0 + lrowA) * K + gpA * 8;
        srcAl = Al + (size_t)(m0 + lrowA) * K + gpA * 8;
    }

    const int agsel = lane >> 4;
    const int rowA  = wm * (BM / 2) + (lane & 15);
    const uint32_t offA = rowA * 64 + ((agsel ^ ((rowA >> 1) & 3)) << 4);
    const int nr    = (lane & 7) + ((lane >> 4) << 3);
    const int kgsel = (lane >> 3) & 1;
    const int rowB  = wn * 32 + nr;
    const uint32_t offB = BOFF + rowB * 64 + ((kgsel ^ ((rowB >> 1) & 3)) << 4);

    const int T = K / TCK;

    auto load_chunk = [&](int stage, int k0) {
        const uint32_t sb_ = smb + stage * STAGE;
        if constexpr (BM == 128) {
            cp_async16s(sb_ + dstA0,         srcAh + k0);
            cp_async16s(sb_ + dstA1,         srcAh + k0 + 8);
            cp_async16s(sb_ + ALOFF + dstA0, srcAl + k0);
            cp_async16s(sb_ + ALOFF + dstA1, srcAl + k0 + 8);
        } else {
            cp_async16s(sb_ + dstA0,         srcAh + k0);
            cp_async16s(sb_ + ALOFF + dstA0, srcAl + k0);
        }
        cp_async16s(sb_ + dstB0,        srcBh + k0);
        cp_async16s(sb_ + dstB1,        srcBh + k0 + 8);
        cp_async16s(sb_ + 8192 + dstB0, srcBl + k0);
        cp_async16s(sb_ + 8192 + dstB1, srcBl + k0 + 8);
        cp_commit();
    };

    load_chunk(0, 0);
    load_chunk(1, TCK);

    float acc[TM][4][4];
    #pragma unroll
    for (int t = 0; t < TM; ++t)
        #pragma unroll
        for (int j = 0; j < 4; ++j)
            #pragma unroll
            for (int q = 0; q < 4; ++q) acc[t][j][q] = 0.f;

    for (int i = 0; i < T; ++i) {
        asm volatile("cp.async.wait_group 1;\n" ::: "memory");
        __syncthreads();

        if (i + 2 < T) load_chunk((i + 2) % 3, (i + 2) * TCK);
        else           cp_commit();

        const uint32_t sb = smb + (i % 3) * STAGE;
        #pragma unroll
        for (int ks = 0; ks < 2; ++ks) {
            const uint32_t kx = ks * 32;
            uint32_t ah_[TM][4], al_[TM][4];
            #pragma unroll
            for (int t = 0; t < TM; ++t) {
                const uint32_t oa = (offA + t * 1024) ^ kx;
                ldsm4(ah_[t], sb + oa);
                ldsm4(al_[t], sb + ALOFF + oa);
            }
            #pragma unroll
            for (int p = 0; p < 2; ++p) {
                uint32_t bh_[4], bl_[4];
                const uint32_t ob = (offB + p * 1024) ^ kx;
                ldsm4(bh_, sb + ob);
                ldsm4(bl_, sb + ob + 8192);
                #pragma unroll
                for (int t = 0; t < TM; ++t) {
                    mma16816(acc[t][2 * p],     ah_[t], bh_);
                    mma16816(acc[t][2 * p + 1], ah_[t], bh_ + 2);
                    mma16816(acc[t][2 * p],     al_[t], bh_);
                    mma16816(acc[t][2 * p + 1], al_[t], bh_ + 2);
                    mma16816(acc[t][2 * p],     ah_[t], bl_);
                    mma16816(acc[t][2 * p + 1], ah_[t], bl_ + 2);
                }
            }
        }
    }

    // ---- epilogue
    const int g  = lane >> 2;
    const int tg = lane & 3;
    #pragma unroll
    for (int t = 0; t < TM; ++t) {
        const int row = m0 + wm * (BM / 2) + t * 16 + g;
        #pragma unroll
        for (int j = 0; j < 4; ++j) {
            const int col = n0 + wn * 32 + j * 8 + 2 * tg;
            if (col < N) {
                float c0 = acc[t][j][0], c1 = acc[t][j][1];
                float c2 = acc[t][j][2], c3 = acc[t][j][3];
                if (ACT == ACT_SOFTPLUS) {
                    c0 = fmaxf(c0, 0.f) + __logf(1.f + __expf(-fabsf(c0)));
                    c1 = fmaxf(c1, 0.f) + __logf(1.f + __expf(-fabsf(c1)));
                    c2 = fmaxf(c2, 0.f) + __logf(1.f + __expf(-fabsf(c2)));
                    c3 = fmaxf(c3, 0.f) + __logf(1.f + __expf(-fabsf(c3)));
                }
                if (ACT == ACT_RESADD) {
                    const float2 r0 = *reinterpret_cast<const float2*>(
                        &Res[(size_t)row * ldr + col]);
                    const float2 r1 = *reinterpret_cast<const float2*>(
                        &Res[(size_t)(row + 8) * ldr + col]);
                    c0 += r0.x; c1 += r0.y; c2 += r1.x; c3 += r1.y;
                }
                const bool storef = SPLIT ? (col >= DINNER) : true;
                if (storef) {
                    *reinterpret_cast<float2*>(&D[(size_t)row * ldd + col]) =
                        make_float2(c0, c1);
                    *reinterpret_cast<float2*>(&D[(size_t)(row + 8) * ldd + col]) =
                        make_float2(c2, c3);
                }
                if (SPLIT && col < DINNER) {
                    split2(&Sh[(size_t)row * DINNER + col],
                           &Sl[(size_t)row * DINNER + col], c0, c1);
                    split2(&Sh[(size_t)(row + 8) * DINNER + col],
                           &Sl[(size_t)(row + 8) * DINNER + col], c2, c3);
                }
            }
        }
    }
}

// ---------------- chunked parallel selective scan ----------------
__global__ __launch_bounds__(256)
void scan_p1(const float* __restrict__ dt, const float* __restrict__ xs,
             const float* __restrict__ ssm, const float* __restrict__ A_log,
             float* __restrict__ P, float* __restrict__ Q) {
    __shared__ float Bsh[GSEG][DSTATE];
    const int b = blockIdx.z, s = blockIdx.y;
    const int d = blockIdx.x * 256 + threadIdx.x;
    const int tok0 = b * SEQ + s * GSEG;

    for (int v = threadIdx.x; v < GSEG * DSTATE; v += 256) {
        const int l = v >> 4, n = v & 15;
        Bsh[l][n] = ssm[(tok0 + l) * XW + DINNER + n];
    }
    __syncthreads();

    float Ac[DSTATE];
    #pragma unroll
    for (int q = 0; q < 4; ++q) {
        const float4 v = reinterpret_cast<const float4*>(&A_log[d * DSTATE])[q];
        Ac[4 * q + 0] = -__expf(v.x);  Ac[4 * q + 1] = -__expf(v.y);
        Ac[4 * q + 2] = -__expf(v.z);  Ac[4 * q + 3] = -__expf(v.w);
    }

    float h[DSTATE];
    #pragma unroll
    for (int n = 0; n < DSTATE; ++n) h[n] = 0.f;
    float sdt = 0.f;

    for (int l = 0; l < GSEG; ++l) {
        const float dtv = dt[(tok0 + l) * DINNER + d];
        const float xv  = xs[(tok0 + l) * DINNER + d];
        sdt += dtv;
        const float dtx = dtv * xv;
        #pragma unroll
        for (int n = 0; n < DSTATE; ++n)
            h[n] = fmaf(__expf(Ac[n] * dtv), h[n], dtx * Bsh[l][n]);
    }

    const int basei = ((b * NSEG + s) * DSTATE) * DINNER + d;
    #pragma unroll
    for (int n = 0; n < DSTATE; ++n) {
        P[basei + n * DINNER] = __expf(Ac[n] * sdt);
        Q[basei + n * DINNER] = h[n];
    }
}

__global__ void scan_combine(const float* __restrict__ P,
                             const float* __restrict__ Q,
                             float* __restrict__ H) {
    const int t = blockIdx.x * 256 + threadIdx.x;
    const int d = t & (DINNER - 1);
    const int n = (t >> 11) & 15;
    const int b = t >> 15;
    float h = 0.f;
    for (int s = 0; s < NSEG; ++s) {
        const int off = ((b * NSEG + s) * DSTATE + n) * DINNER + d;
        H[off] = h;
        h = fmaf(P[off], h, Q[off]);
    }
}

__global__ __launch_bounds__(256)
void scan_p2(const float* __restrict__ dt, const float* __restrict__ xs,
             const float* __restrict__ ssm, const float* __restrict__ xr,
             const float* __restrict__ A_log, const float* __restrict__ H,
             __nv_bfloat16* __restrict__ yh, __nv_bfloat16* __restrict__ yl) {
    __shared__ float Bsh[GSEG][DSTATE];
    __shared__ float Csh[GSEG][DSTATE];
    const int b = blockIdx.z, s = blockIdx.y;
    const int d = blockIdx.x * 256 + threadIdx.x;
    const int tok0 = b * SEQ + s * GSEG;

    for (int v = threadIdx.x; v < GSEG * DSTATE * 2; v += 256) {
        const int l = v >> 5, j = v & 31;
        const float val = ssm[(tok0 + l) * XW + DINNER + j];
        if (j < DSTATE) Bsh[l][j] = val;
        else            Csh[l][j - DSTATE] = val;
    }
    __syncthreads();

    float Ac[DSTATE];
    #pragma unroll
    for (int q = 0; q < 4; ++q) {
        const float4 v = reinterpret_cast<const float4*>(&A_log[d * DSTATE])[q];
        Ac[4 * q + 0] = -__expf(v.x);  Ac[4 * q + 1] = -__expf(v.y);
        Ac[4 * q + 2] = -__expf(v.z);  Ac[4 * q + 3] = -__expf(v.w);
    }

    const int basei = ((b * NSEG + s) * DSTATE) * DINNER + d;
    float h[DSTATE];
    #pragma unroll
    for (int n = 0; n < DSTATE; ++n) h[n] = H[basei + n * DINNER];

    for (int l = 0; l < GSEG; ++l) {
        const float dtv = dt[(tok0 + l) * DINNER + d];
        const float xv  = xs[(tok0 + l) * DINNER + d];
        const float dtx = dtv * xv;
        float y = 0.f;
        #pragma unroll
        for (int n = 0; n < DSTATE; ++n) {
            h[n] = fmaf(__expf(Ac[n] * dtv), h[n], dtx * Bsh[l][n]);
            y = fmaf(h[n], Csh[l][n], y);
        }
        const float r = xr[(tok0 + l) * (2 * DINNER) + DINNER + d];
        const float v = y * fast_silu(r);
        const __nv_bfloat16 hi = __float2bfloat16(v);
        yh[(tok0 + l) * DINNER + d] = hi;
        yl[(tok0 + l) * DINNER + d] = __float2bfloat16(v - __bfloat162float(hi));
    }
}

// ---------------- launch ----------------
extern "C" void kernel_launch(void* const* d_in, const int* in_sizes, int n_in,
                              void* d_out, int out_size) {
    const float* x      = (const float*)d_in[0];
    const float* rms_w  = (const float*)d_in[1];
    const float* W_in   = (const float*)d_in[2];
    const float* conv_w = (const float*)d_in[3];
    const float* conv_b = (const float*)d_in[4];
    const float* W_x    = (const float*)d_in[5];
    const float* W_dt   = (const float*)d_in[6];
    const float* A_log  = (const float*)d_in[7];
    const float* W_out  = (const float*)d_in[8];
    float* out = (float*)d_out;

    float *xr, *xs, *ssm, *dtb, *P, *Q, *H;
    __nv_bfloat16 *ah0, *al0, *ah1, *al1;
    __nv_bfloat16 *w1h, *w1l, *w2h, *w2l, *w3h, *w3l, *w4h, *w4l;
    cudaGetSymbolAddress((void**)&xr,  g_xr);
    cudaGetSymbolAddress((void**)&xs,  g_xs);
    cudaGetSymbolAddress((void**)&ssm, g_ssm);
    cudaGetSymbolAddress((void**)&dtb, g_dt);
    cudaGetSymbolAddress((void**)&P,   g_P);
    cudaGetSymbolAddress((void**)&Q,   g_Q);
    cudaGetSymbolAddress((void**)&H,   g_H);
    cudaGetSymbolAddress((void**)&ah0, g_ah0);  cudaGetSymbolAddress((void**)&al0, g_al0);
    cudaGetSymbolAddress((void**)&ah1, g_ah1);  cudaGetSymbolAddress((void**)&al1, g_al1);
    cudaGetSymbolAddress((void**)&w1h, g_w1h);  cudaGetSymbolAddress((void**)&w1l, g_w1l);
    cudaGetSymbolAddress((void**)&w2h, g_w2h);  cudaGetSymbolAddress((void**)&w2l, g_w2l);
    cudaGetSymbolAddress((void**)&w3h, g_w3h);  cudaGetSymbolAddress((void**)&w3l, g_w3l);
    cudaGetSymbolAddress((void**)&w4h, g_w4h);  cudaGetSymbolAddress((void**)&w4l, g_w4l);

    constexpr int SM128 = 3 * (128 * 128 + 16384);   // 98304
    constexpr int SM64  = 3 * (64 * 128 + 16384);    // 73728

    static bool attr_done = false;
    if (!attr_done) {
        cudaFuncSetAttribute(tcgemm_kernel<ACT_NONE, 0, 128>,
            cudaFuncAttributeMaxDynamicSharedMemorySize, SM128);
        cudaFuncSetAttribute(tcgemm_kernel<ACT_NONE, 1, 128>,
            cudaFuncAttributeMaxDynamicSharedMemorySize, SM128);
        cudaFuncSetAttribute(tcgemm_kernel<ACT_SOFTPLUS, 0, 128>,
            cudaFuncAttributeMaxDynamicSharedMemorySize, SM128);
        cudaFuncSetAttribute(tcgemm_kernel<ACT_RESADD, 0, 64>,
            cudaFuncAttributeMaxDynamicSharedMemorySize, SM64);
        attr_done = true;
    }

    // weight split+transpose, single launch
    wsplit_all_kernel<<<14592, dim3(32, 8)>>>(W_in, W_x, W_dt, W_out,
        w1h, w1l, w2h, w2l, w3h, w3l, w4h, w4l);

    // 1. RMSNorm -> split buf0
    rmsnorm_split_kernel<<<NTOK, 256>>>(x, rms_w, ah0, al0);

    // 2. xr = xn @ W_in   [2048,4096], K=1024
    tcgemm_kernel<ACT_NONE, 0, 128><<<dim3(32, 16), 256, SM128>>>(
        ah0, al0, w1h, w1l, xr, nullptr, nullptr, nullptr, 4096, 1024, 4096, 0);

    // 3. conv + silu -> xs fp32 + split buf1
    conv_silu_kernel<<<(NTOK * DINNER / 4) / 256, 256>>>(xr, conv_w, conv_b,
                                                         xs, ah1, al1);

    // 4. x_ssm = xs @ W_x   [2048,2080], K=2048; dt-cols split -> buf0
    tcgemm_kernel<ACT_NONE, 1, 128><<<dim3(17, 16), 256, SM128>>>(
        ah1, al1, w2h, w2l, ssm, nullptr, ah0, al0, XW, 2048, XW, 0);

    // 5. dt = softplus(ssm_dt @ W_dt)   K=2048
    tcgemm_kernel<ACT_SOFTPLUS, 0, 128><<<dim3(16, 16), 256, SM128>>>(
        ah0, al0, w3h, w3l, dtb, nullptr, nullptr, nullptr, 2048, 2048, 2048, 0);

    // 6. chunked parallel scan; p2 writes split yz -> buf1
    scan_p1<<<dim3(DINNER / 256, NSEG, BATCH), 256>>>(dtb, xs, ssm, A_log, P, Q);
    scan_combine<<<(BATCH * DSTATE * DINNER) / 256, 256>>>(P, Q, H);
    scan_p2<<<dim3(DINNER / 256, NSEG, BATCH), 256>>>(dtb, xs, ssm, xr, A_log, H,
                                                      ah1, al1);

    // 7. out = x + yz @ W_out   [2048,1024], K=2048  (BM=64 -> 256 CTAs)
    tcgemm_kernel<ACT_RESADD, 0, 64><<<dim3(8, 32), 256, SM64>>>(
        ah1, al1, w4h, w4l, out, x, nullptr, nullptr, 1024, 2048, 1024, 1024);
}

// round 11
// speedup vs baseline: 2.4432x; 1.0777x over previous
#include <cuda_runtime.h>
#include <cuda_bf16.h>
#include <math.h>
#include <stdint.h>

// ---------------- problem constants ----------------
#define BATCH    2
#define SEQ      1024
#define DMODEL   1024
#define DINNER   2048
#define DSTATE   16
#define NTOK     (BATCH * SEQ)          // 2048
#define XW       (DINNER + 2 * DSTATE)  // 2080
#define NSEG     32
#define GSEG     32

// ---------------- fp32 scratch ----------------
__device__ float g_xr [NTOK * 2 * DINNER];
__device__ float g_xs [NTOK * DINNER];
__device__ float g_ssm[NTOK * XW];      // only B/C cols (2048..2079) used now
__device__ float g_dt [NTOK * DINNER];
__device__ float g_P  [BATCH * NSEG * DSTATE * DINNER];
__device__ float g_Q  [BATCH * NSEG * DSTATE * DINNER];
__device__ float g_H  [BATCH * NSEG * DSTATE * DINNER];

// ---------------- bf16 split buffers ----------------
__device__ __nv_bfloat16 g_ah0[NTOK * DINNER], g_al0[NTOK * DINNER];
__device__ __nv_bfloat16 g_ah1[NTOK * DINNER], g_al1[NTOK * DINNER];
__device__ __nv_bfloat16 g_w1h[4096 * 1024], g_w1l[4096 * 1024];   // W_in^T
__device__ __nv_bfloat16 g_w2h[2176 * 2048], g_w2l[2176 * 2048];   // [Wc | W_x_BC]^T
__device__ __nv_bfloat16 g_w3h[2048 * 2048], g_w3l[2048 * 2048];   // W_dt^T
__device__ __nv_bfloat16 g_w4h[1024 * 2048], g_w4l[1024 * 2048];   // W_out^T
__device__ __nv_bfloat16 g_wxd_h[2048 * 2048], g_wxd_l[2048 * 2048]; // W_x[:, :2048] direct

// ---------------- helpers ----------------
__device__ __forceinline__ uint32_t smem_u32(const void* p) {
    uint32_t a;
    asm("{ .reg .u64 t; cvta.to.shared.u64 t, %1; cvt.u32.u64 %0, t; }"
        : "=r"(a) : "l"(p));
    return a;
}
__device__ __forceinline__ void cp_async16s(uint32_t saddr, const void* gptr) {
    asm volatile("cp.async.cg.shared.global [%0], [%1], 16;\n"
                 :: "r"(saddr), "l"(gptr));
}
__device__ __forceinline__ void cp_commit() {
    asm volatile("cp.async.commit_group;\n");
}
__device__ __forceinline__ void ldsm4(uint32_t* r, uint32_t a) {
    asm volatile("ldmatrix.sync.aligned.m8n8.x4.shared.b16 {%0,%1,%2,%3}, [%4];"
                 : "=r"(r[0]), "=r"(r[1]), "=r"(r[2]), "=r"(r[3]) : "r"(a));
}
__device__ __forceinline__ void mma16816(float* c, const uint32_t* a,
                                         const uint32_t* b) {
    asm volatile(
        "mma.sync.aligned.m16n8k16.row.col.f32.bf16.bf16.f32 "
        "{%0,%1,%2,%3}, {%4,%5,%6,%7}, {%8,%9}, {%0,%1,%2,%3};"
        : "+f"(c[0]), "+f"(c[1]), "+f"(c[2]), "+f"(c[3])
        : "r"(a[0]), "r"(a[1]), "r"(a[2]), "r"(a[3]), "r"(b[0]), "r"(b[1]));
}
__device__ __forceinline__ void split2(__nv_bfloat16* h, __nv_bfloat16* l,
                                       float v0, float v1) {
    const __nv_bfloat16 h0 = __float2bfloat16(v0);
    const __nv_bfloat16 h1 = __float2bfloat16(v1);
    __nv_bfloat162 hh; hh.x = h0; hh.y = h1;
    __nv_bfloat162 ll;
    ll.x = __float2bfloat16(v0 - __bfloat162float(h0));
    ll.y = __float2bfloat16(v1 - __bfloat162float(h1));
    *reinterpret_cast<__nv_bfloat162*>(h) = hh;
    *reinterpret_cast<__nv_bfloat162*>(l) = ll;
}
__device__ __forceinline__ float fast_silu(float a) {
    return __fdividef(a, 1.f + __expf(-a));
}

// ---------------- RMSNorm, split output ----------------
__global__ void rmsnorm_split_kernel(const float* __restrict__ x,
                                     const float* __restrict__ w,
                                     __nv_bfloat16* __restrict__ oh,
                                     __nv_bfloat16* __restrict__ ol) {
    const int t   = blockIdx.x;
    const int tid = threadIdx.x;
    const float4 v = reinterpret_cast<const float4*>(x + t * DMODEL)[tid];
    float s = v.x * v.x + v.y * v.y + v.z * v.z + v.w * v.w;
    #pragma unroll
    for (int o = 16; o; o >>= 1) s += __shfl_xor_sync(0xffffffffu, s, o);
    __shared__ float red[8];
    __shared__ float sscale;
    if ((tid & 31) == 0) red[tid >> 5] = s;
    __syncthreads();
    if (tid == 0) {
        float tot = 0.f;
        #pragma unroll
        for (int i = 0; i < 8; ++i) tot += red[i];
        sscale = rsqrtf(tot * (1.0f / DMODEL) + 1e-5f);
    }
    __syncthreads();
    const float sc = sscale;
    const float4 wv = reinterpret_cast<const float4*>(w)[tid];
    const int base = t * DMODEL + tid * 4;
    split2(&oh[base],     &ol[base],     v.x * sc * wv.x, v.y * sc * wv.y);
    split2(&oh[base + 2], &ol[base + 2], v.z * sc * wv.z, v.w * sc * wv.w);
}

// ---------------- depthwise causal conv + SiLU (float4/thread) ----------------
__global__ void conv_silu_kernel(const float* __restrict__ xr,
                                 const float* __restrict__ cw,
                                 const float* __restrict__ cb,
                                 float* __restrict__ xs,
                                 __nv_bfloat16* __restrict__ oh,
                                 __nv_bfloat16* __restrict__ ol) {
    const int idx = (blockIdx.x * blockDim.x + threadIdx.x) * 4;
    const int d   = idx & (DINNER - 1);
    const int tok = idx >> 11;
    const int l   = tok & (SEQ - 1);
    const float4* cw4 = reinterpret_cast<const float4*>(cw);
    const float4 w0 = cw4[d];
    const float4 w1 = cw4[d + 1];
    const float4 w2 = cw4[d + 2];
    const float4 w3 = cw4[d + 3];
    float4 a = reinterpret_cast<const float4*>(cb)[d >> 2];
    #pragma unroll
    for (int j = 0; j < 4; ++j) {
        const int ls = l - 3 + j;
        if (ls >= 0) {
            const float4 xv = *reinterpret_cast<const float4*>(
                &xr[(tok + j - 3) * (2 * DINNER) + d]);
            const float t0 = (j == 0) ? w0.x : (j == 1) ? w0.y : (j == 2) ? w0.z : w0.w;
            const float t1 = (j == 0) ? w1.x : (j == 1) ? w1.y : (j == 2) ? w1.z : w1.w;
            const float t2 = (j == 0) ? w2.x : (j == 1) ? w2.y : (j == 2) ? w2.z : w2.w;
            const float t3 = (j == 0) ? w3.x : (j == 1) ? w3.y : (j == 2) ? w3.z : w3.w;
            a.x = fmaf(t0, xv.x, a.x);
            a.y = fmaf(t1, xv.y, a.y);
            a.z = fmaf(t2, xv.z, a.z);
            a.w = fmaf(t3, xv.w, a.w);
        }
    }
    a.x = fast_silu(a.x);  a.y = fast_silu(a.y);
    a.z = fast_silu(a.z);  a.w = fast_silu(a.w);
    *reinterpret_cast<float4*>(&xs[idx]) = a;
    split2(&oh[idx],     &ol[idx],     a.x, a.y);
    split2(&oh[idx + 2], &ol[idx + 2], a.z, a.w);
}

// ---------------- merged weight split (5 segments) ----------------
// [0,4096)      W_in  transpose -> w1 (K=1024, N=4096)
// [4096,4352)   W_x B/C cols transpose -> w2 rows 2048..2175 (pad zeros)
// [4352,8448)   W_dt  transpose -> w3 (2048^2)
// [8448,10496)  W_out transpose -> w4 (K=2048, N=1024)
// [10496,14592) W_x[:, :2048] DIRECT split -> wxd (2048^2)
__global__ void wsplit_all_kernel(const float* __restrict__ W1,
                                  const float* __restrict__ W2,
                                  const float* __restrict__ W3,
                                  const float* __restrict__ W4,
                                  __nv_bfloat16* __restrict__ w1h, __nv_bfloat16* __restrict__ w1l,
                                  __nv_bfloat16* __restrict__ w2h, __nv_bfloat16* __restrict__ w2l,
                                  __nv_bfloat16* __restrict__ w3h, __nv_bfloat16* __restrict__ w3l,
                                  __nv_bfloat16* __restrict__ w4h, __nv_bfloat16* __restrict__ w4l,
                                  __nv_bfloat16* __restrict__ wdh, __nv_bfloat16* __restrict__ wdl) {
    const int id = blockIdx.x;
    const int tx = threadIdx.x, ty = threadIdx.y;   // 32 x 8

    if (id >= 10496) {   // direct split of W_x[:, :2048]
        const int rel = id - 10496;
        const int j0 = (rel & 63) * 32, k0 = (rel >> 6) * 32;
        #pragma unroll
        for (int r = 0; r < 4; ++r) {
            const int k = k0 + ty + 8 * r, j = j0 + tx;
            const float v = W2[(size_t)k * XW + j];
            const __nv_bfloat16 hi = __float2bfloat16(v);
            wdh[(size_t)k * 2048 + j] = hi;
            wdl[(size_t)k * 2048 + j] = __float2bfloat16(v - __bfloat162float(hi));
        }
        return;
    }

    const float* W; __nv_bfloat16 *Th, *Tl;
    int K, N, ld, n0, k0;
    if (id < 4096) {
        W = W1; Th = w1h; Tl = w1l; K = 1024; N = 4096; ld = 4096;
        n0 = (id & 127) * 32; k0 = (id >> 7) * 32;
    } else if (id < 4352) {
        const int rel = id - 4096;
        W = W2; Th = w2h; Tl = w2l; K = 2048; N = XW; ld = XW;
        n0 = 2048 + (rel & 3) * 32; k0 = (rel >> 2) * 32;
    } else if (id < 8448) {
        const int rel = id - 4352;
        W = W3; Th = w3h; Tl = w3l; K = 2048; N = 2048; ld = 2048;
        n0 = (rel & 63) * 32; k0 = (rel >> 6) * 32;
    } else {
        const int rel = id - 8448;
        W = W4; Th = w4h; Tl = w4l; K = 2048; N = 1024; ld = 1024;
        n0 = (rel & 31) * 32; k0 = (rel >> 5) * 32;
    }

    __shared__ float tile[32][33];
    #pragma unroll
    for (int r = 0; r < 4; ++r) {
        const int k = k0 + ty + 8 * r, n = n0 + tx;
        tile[ty + 8 * r][tx] = (n < N) ? W[(size_t)k * ld + n] : 0.f;
    }
    __syncthreads();
    #pragma unroll
    for (int r = 0; r < 4; ++r) {
        const int nrow = n0 + ty + 8 * r, k = k0 + tx;
        const float v = tile[tx][ty + 8 * r];
        const __nv_bfloat16 hi = __float2bfloat16(v);
        Th[(size_t)nrow * K + k] = hi;
        Tl[(size_t)nrow * K + k] = __float2bfloat16(v - __bfloat162float(hi));
    }
}

// ---------------- mma.sync bf16-split GEMM (templated BM) ----------------
#define TCK 32

#define ACT_NONE     0
#define ACT_RESADD   2
#define ACT_DTBC     3    // col<2048: softplus->D(dt); col>=2048: ->Res(ssm B/C)

template <int ACT, int SPLIT, int BM>
__global__ __launch_bounds__(256, 2)
void tcgemm_kernel(const __nv_bfloat16* __restrict__ Ah,
                   const __nv_bfloat16* __restrict__ Al,
                   const __nv_bfloat16* __restrict__ Bh,
                   const __nv_bfloat16* __restrict__ Bl,
                   float* __restrict__ D, const float* __restrict__ Res,
                   __nv_bfloat16* __restrict__ Sh, __nv_bfloat16* __restrict__ Sl,
                   int N, int K, int ldd, int ldr) {
    constexpr int TM    = BM / 32;
    constexpr int ALOFF = BM * 64;
    constexpr int BOFF  = 2 * BM * 64;
    constexpr int STAGE = BM * 128 + 16384;

    extern __shared__ unsigned char sm[];
    const uint32_t smb = smem_u32(sm);

    const int tid  = threadIdx.x;
    const int lane = tid & 31;
    const int wid  = tid >> 5;
    const int wm   = wid >> 2;
    const int wn   = wid & 3;
    const int m0   = blockIdx.y * BM;
    const int n0   = blockIdx.x * 128;

    const int lrowB = tid >> 1;
    const int gpB   = (tid & 1) * 2;
    const int swB   = (lrowB >> 1) & 3;
    const uint32_t dstB0 = BOFF + lrowB * 64 + (((gpB + 0) ^ swB) << 4);
    const uint32_t dstB1 = BOFF + lrowB * 64 + (((gpB + 1) ^ swB) << 4);
    const __nv_bfloat16* srcBh = Bh + (size_t)(n0 + lrowB) * K + gpB * 8;
    const __nv_bfloat16* srcBl = Bl + (size_t)(n0 + lrowB) * K + gpB * 8;

    uint32_t dstA0, dstA1 = 0;
    const __nv_bfloat16 *srcAh, *srcAl;
    if constexpr (BM == 128) {
        dstA0 = lrowB * 64 + (((gpB + 0) ^ swB) << 4);
        dstA1 = lrowB * 64 + (((gpB + 1) ^ swB) << 4);
        srcAh = Ah + (size_t)(m0 + lrowB) * K + gpB * 8;
        srcAl = Al + (size_t)(m0 + lrowB) * K + gpB * 8;
    } else {
        const int lrowA = tid >> 2;
        const int gpA   = tid & 3;
        dstA0 = lrowA * 64 + ((gpA ^ ((lrowA >> 1) & 3)) << 4);
        srcAh = Ah + (size_t)(m0 + lrowA) * K + gpA * 8;
        srcAl = Al + (size_t)(m0 + lrowA) * K + gpA * 8;
    }

    const int agsel = lane >> 4;
    const int rowA  = wm * (BM / 2) + (lane & 15);
    const uint32_t offA = rowA * 64 + ((agsel ^ ((rowA >> 1) & 3)) << 4);
    const int nr    = (lane & 7) + ((lane >> 4) << 3);
    const int kgsel = (lane >> 3) & 1;
    const int rowB  = wn * 32 + nr;
    const uint32_t offB = BOFF + rowB * 64 + ((kgsel ^ ((rowB >> 1) & 3)) << 4);

    const int T = K / TCK;

    auto load_chunk = [&](int stage, int k0) {
        const uint32_t sb_ = smb + stage * STAGE;
        if constexpr (BM == 128) {
            cp_async16s(sb_ + dstA0,         srcAh + k0);
            cp_async16s(sb_ + dstA1,         srcAh + k0 + 8);
            cp_async16s(sb_ + ALOFF + dstA0, srcAl + k0);
            cp_async16s(sb_ + ALOFF + dstA1, srcAl + k0 + 8);
        } else {
            cp_async16s(sb_ + dstA0,         srcAh + k0);
            cp_async16s(sb_ + ALOFF + dstA0, srcAl + k0);
        }
        cp_async16s(sb_ + dstB0,        srcBh + k0);
        cp_async16s(sb_ + dstB1,        srcBh + k0 + 8);
        cp_async16s(sb_ + 8192 + dstB0, srcBl + k0);
        cp_async16s(sb_ + 8192 + dstB1, srcBl + k0 + 8);
        cp_commit();
    };

    load_chunk(0, 0);
    load_chunk(1, TCK);

    float acc[TM][4][4];
    #pragma unroll
    for (int t = 0; t < TM; ++t)
        #pragma unroll
        for (int j = 0; j < 4; ++j)
            #pragma unroll
            for (int q = 0; q < 4; ++q) acc[t][j][q] = 0.f;

    for (int i = 0; i < T; ++i) {
        asm volatile("cp.async.wait_group 1;\n" ::: "memory");
        __syncthreads();

        if (i + 2 < T) load_chunk((i + 2) % 3, (i + 2) * TCK);
        else           cp_commit();

        const uint32_t sb = smb + (i % 3) * STAGE;
        #pragma unroll
        for (int ks = 0; ks < 2; ++ks) {
            const uint32_t kx = ks * 32;
            uint32_t ah_[TM][4], al_[TM][4];
            #pragma unroll
            for (int t = 0; t < TM; ++t) {
                const uint32_t oa = (offA + t * 1024) ^ kx;
                ldsm4(ah_[t], sb + oa);
                ldsm4(al_[t], sb + ALOFF + oa);
            }
            #pragma unroll
            for (int p = 0; p < 2; ++p) {
                uint32_t bh_[4], bl_[4];
                const uint32_t ob = (offB + p * 1024) ^ kx;
                ldsm4(bh_, sb + ob);
                ldsm4(bl_, sb + ob + 8192);
                #pragma unroll
                for (int t = 0; t < TM; ++t) {
                    mma16816(acc[t][2 * p],     ah_[t], bh_);
                    mma16816(acc[t][2 * p + 1], ah_[t], bh_ + 2);
                    mma16816(acc[t][2 * p],     al_[t], bh_);
                    mma16816(acc[t][2 * p + 1], al_[t], bh_ + 2);
                    mma16816(acc[t][2 * p],     ah_[t], bl_);
                    mma16816(acc[t][2 * p + 1], ah_[t], bl_ + 2);
                }
            }
        }
    }

    // ---- epilogue
    const int g  = lane >> 2;
    const int tg = lane & 3;
    #pragma unroll
    for (int t = 0; t < TM; ++t) {
        const int row = m0 + wm * (BM / 2) + t * 16 + g;
        #pragma unroll
        for (int j = 0; j < 4; ++j) {
            const int col = n0 + wn * 32 + j * 8 + 2 * tg;
            if (col < N) {
                float c0 = acc[t][j][0], c1 = acc[t][j][1];
                float c2 = acc[t][j][2], c3 = acc[t][j][3];
                if (ACT == ACT_DTBC) {
                    if (col < DINNER) {
                        c0 = fmaxf(c0, 0.f) + __logf(1.f + __expf(-fabsf(c0)));
                        c1 = fmaxf(c1, 0.f) + __logf(1.f + __expf(-fabsf(c1)));
                        c2 = fmaxf(c2, 0.f) + __logf(1.f + __expf(-fabsf(c2)));
                        c3 = fmaxf(c3, 0.f) + __logf(1.f + __expf(-fabsf(c3)));
                        *reinterpret_cast<float2*>(&D[(size_t)row * ldd + col]) =
                            make_float2(c0, c1);
                        *reinterpret_cast<float2*>(&D[(size_t)(row + 8) * ldd + col]) =
                            make_float2(c2, c3);
                    } else {
                        float* bc = const_cast<float*>(Res);
                        *reinterpret_cast<float2*>(&bc[(size_t)row * ldr + col]) =
                            make_float2(c0, c1);
                        *reinterpret_cast<float2*>(&bc[(size_t)(row + 8) * ldr + col]) =
                            make_float2(c2, c3);
                    }
                    continue;
                }
                if (ACT == ACT_RESADD) {
                    const float2 r0 = *reinterpret_cast<const float2*>(
                        &Res[(size_t)row * ldr + col]);
                    const float2 r1 = *reinterpret_cast<const float2*>(
                        &Res[(size_t)(row + 8) * ldr + col]);
                    c0 += r0.x; c1 += r0.y; c2 += r1.x; c3 += r1.y;
                }
                const bool storef = SPLIT ? (col >= DINNER) : true;
                if (storef) {
                    *reinterpret_cast<float2*>(&D[(size_t)row * ldd + col]) =
                        make_float2(c0, c1);
                    *reinterpret_cast<float2*>(&D[(size_t)(row + 8) * ldd + col]) =
                        make_float2(c2, c3);
                }
                if (SPLIT && col < DINNER) {
                    split2(&Sh[(size_t)row * DINNER + col],
                           &Sl[(size_t)row * DINNER + col], c0, c1);
                    split2(&Sh[(size_t)(row + 8) * DINNER + col],
                           &Sl[(size_t)(row + 8) * DINNER + col], c2, c3);
                }
            }
        }
    }
}

// ---------------- chunked parallel selective scan ----------------
__global__ __launch_bounds__(256)
void scan_p1(const float* __restrict__ dt, const float* __restrict__ xs,
             const float* __restrict__ ssm, const float* __restrict__ A_log,
             float* __restrict__ P, float* __restrict__ Q) {
    __shared__ float Bsh[GSEG][DSTATE];
    const int b = blockIdx.z, s = blockIdx.y;
    const int d = blockIdx.x * 256 + threadIdx.x;
    const int tok0 = b * SEQ + s * GSEG;

    for (int v = threadIdx.x; v < GSEG * DSTATE; v += 256) {
        const int l = v >> 4, n = v & 15;
        Bsh[l][n] = ssm[(tok0 + l) * XW + DINNER + n];
    }
    __syncthreads();

    float Ac[DSTATE];
    #pragma unroll
    for (int q = 0; q < 4; ++q) {
        const float4 v = reinterpret_cast<const float4*>(&A_log[d * DSTATE])[q];
        Ac[4 * q + 0] = -__expf(v.x);  Ac[4 * q + 1] = -__expf(v.y);
        Ac[4 * q + 2] = -__expf(v.z);  Ac[4 * q + 3] = -__expf(v.w);
    }

    float h[DSTATE];
    #pragma unroll
    for (int n = 0; n < DSTATE; ++n) h[n] = 0.f;
    float sdt = 0.f;

    for (int l = 0; l < GSEG; ++l) {
        const float dtv = dt[(tok0 + l) * DINNER + d];
        const float xv  = xs[(tok0 + l) * DINNER + d];
        sdt += dtv;
        const float dtx = dtv * xv;
        #pragma unroll
        for (int n = 0; n < DSTATE; ++n)
            h[n] = fmaf(__expf(Ac[n] * dtv), h[n], dtx * Bsh[l][n]);
    }

    const int basei = ((b * NSEG + s) * DSTATE) * DINNER + d;
    #pragma unroll
    for (int n = 0; n < DSTATE; ++n) {
        P[basei + n * DINNER] = __expf(Ac[n] * sdt);
        Q[basei + n * DINNER] = h[n];
    }
}

__global__ void scan_combine(const float* __restrict__ P,
                             const float* __restrict__ Q,
                             float* __restrict__ H) {
    const int t = blockIdx.x * 256 + threadIdx.x;
    const int d = t & (DINNER - 1);
    const int n = (t >> 11) & 15;
    const int b = t >> 15;
    float h = 0.f;
    for (int s = 0; s < NSEG; ++s) {
        const int off = ((b * NSEG + s) * DSTATE + n) * DINNER + d;
        H[off] = h;
        h = fmaf(P[off], h, Q[off]);
    }
}

__global__ __launch_bounds__(256)
void scan_p2(const float* __restrict__ dt, const float* __restrict__ xs,
             const float* __restrict__ ssm, const float* __restrict__ xr,
             const float* __restrict__ A_log, const float* __restrict__ H,
             __nv_bfloat16* __restrict__ yh, __nv_bfloat16* __restrict__ yl) {
    __shared__ float Bsh[GSEG][DSTATE];
    __shared__ float Csh[GSEG][DSTATE];
    const int b = blockIdx.z, s = blockIdx.y;
    const int d = blockIdx.x * 256 + threadIdx.x;
    const int tok0 = b * SEQ + s * GSEG;

    for (int v = threadIdx.x; v < GSEG * DSTATE * 2; v += 256) {
        const int l = v >> 5, j = v & 31;
        const float val = ssm[(tok0 + l) * XW + DINNER + j];
        if (j < DSTATE) Bsh[l][j] = val;
        else            Csh[l][j - DSTATE] = val;
    }
    __syncthreads();

    float Ac[DSTATE];
    #pragma unroll
    for (int q = 0; q < 4; ++q) {
        const float4 v = reinterpret_cast<const float4*>(&A_log[d * DSTATE])[q];
        Ac[4 * q + 0] = -__expf(v.x);  Ac[4 * q + 1] = -__expf(v.y);
        Ac[4 * q + 2] = -__expf(v.z);  Ac[4 * q + 3] = -__expf(v.w);
    }

    const int basei = ((b * NSEG + s) * DSTATE) * DINNER + d;
    float h[DSTATE];
    #pragma unroll
    for (int n = 0; n < DSTATE; ++n) h[n] = H[basei + n * DINNER];

    for (int l = 0; l < GSEG; ++l) {
        const float dtv = dt[(tok0 + l) * DINNER + d];
        const float xv  = xs[(tok0 + l) * DINNER + d];
        const float dtx = dtv * xv;
        float y = 0.f;
        #pragma unroll
        for (int n = 0; n < DSTATE; ++n) {
            h[n] = fmaf(__expf(Ac[n] * dtv), h[n], dtx * Bsh[l][n]);
            y = fmaf(h[n], Csh[l][n], y);
        }
        const float r = xr[(tok0 + l) * (2 * DINNER) + DINNER + d];
        const float v = y * fast_silu(r);
        const __nv_bfloat16 hi = __float2bfloat16(v);
        yh[(tok0 + l) * DINNER + d] = hi;
        yl[(tok0 + l) * DINNER + d] = __float2bfloat16(v - __bfloat162float(hi));
    }
}

// ---------------- launch ----------------
extern "C" void kernel_launch(void* const* d_in, const int* in_sizes, int n_in,
                              void* d_out, int out_size) {
    const float* x      = (const float*)d_in[0];
    const float* rms_w  = (const float*)d_in[1];
    const float* W_in   = (const float*)d_in[2];
    const float* conv_w = (const float*)d_in[3];
    const float* conv_b = (const float*)d_in[4];
    const float* W_x    = (const float*)d_in[5];
    const float* W_dt   = (const float*)d_in[6];
    const float* A_log  = (const float*)d_in[7];
    const float* W_out  = (const float*)d_in[8];
    float* out = (float*)d_out;

    float *xr, *xs, *ssm, *dtb, *P, *Q, *H;
    __nv_bfloat16 *ah0, *al0, *ah1, *al1;
    __nv_bfloat16 *w1h, *w1l, *w2h, *w2l, *w3h, *w3l, *w4h, *w4l, *wdh, *wdl;
    cudaGetSymbolAddress((void**)&xr,  g_xr);
    cudaGetSymbolAddress((void**)&xs,  g_xs);
    cudaGetSymbolAddress((void**)&ssm, g_ssm);
    cudaGetSymbolAddress((void**)&dtb, g_dt);
    cudaGetSymbolAddress((void**)&P,   g_P);
    cudaGetSymbolAddress((void**)&Q,   g_Q);
    cudaGetSymbolAddress((void**)&H,   g_H);
    cudaGetSymbolAddress((void**)&ah0, g_ah0);  cudaGetSymbolAddress((void**)&al0, g_al0);
    cudaGetSymbolAddress((void**)&ah1, g_ah1);  cudaGetSymbolAddress((void**)&al1, g_al1);
    cudaGetSymbolAddress((void**)&w1h, g_w1h);  cudaGetSymbolAddress((void**)&w1l, g_w1l);
    cudaGetSymbolAddress((void**)&w2h, g_w2h);  cudaGetSymbolAddress((void**)&w2l, g_w2l);
    cudaGetSymbolAddress((void**)&w3h, g_w3h);  cudaGetSymbolAddress((void**)&w3l, g_w3l);
    cudaGetSymbolAddress((void**)&w4h, g_w4h);  cudaGetSymbolAddress((void**)&w4l, g_w4l);
    cudaGetSymbolAddress((void**)&wdh, g_wxd_h); cudaGetSymbolAddress((void**)&wdl, g_wxd_l);

    constexpr int SM128 = 3 * (128 * 128 + 16384);   // 98304
    constexpr int SM64  = 3 * (64 * 128 + 16384);    // 73728

    static cudaStream_t s2 = nullptr;
    static cudaEvent_t evFork = nullptr, evJoin = nullptr;
    if (!s2) {
        cudaFuncSetAttribute(tcgemm_kernel<ACT_NONE, 0, 128>,
            cudaFuncAttributeMaxDynamicSharedMemorySize, SM128);
        cudaFuncSetAttribute(tcgemm_kernel<ACT_NONE, 1, 128>,
            cudaFuncAttributeMaxDynamicSharedMemorySize, SM128);
        cudaFuncSetAttribute(tcgemm_kernel<ACT_DTBC, 0, 128>,
            cudaFuncAttributeMaxDynamicSharedMemorySize, SM128);
        cudaFuncSetAttribute(tcgemm_kernel<ACT_RESADD, 0, 64>,
            cudaFuncAttributeMaxDynamicSharedMemorySize, SM64);
        cudaStreamCreateWithFlags(&s2, cudaStreamNonBlocking);
        cudaEventCreateWithFlags(&evFork, cudaEventDisableTiming);
        cudaEventCreateWithFlags(&evJoin, cudaEventDisableTiming);
    }

    // weight split (all segments), stream 0
    wsplit_all_kernel<<<14592, dim3(32, 8)>>>(W_in, W_x, W_dt, W_out,
        w1h, w1l, w2h, w2l, w3h, w3l, w4h, w4l, wdh, wdl);

    // ---- fork: weight-weight GEMM Wc^T = (W_dt^T) @ (W_x direct) on s2,
    //      split epilogue writes w2h/w2l rows 0..2047.
    cudaEventRecord(evFork, 0);
    cudaStreamWaitEvent(s2, evFork, 0);
    tcgemm_kernel<ACT_NONE, 1, 128><<<dim3(16, 16), 256, SM128, s2>>>(
        w3h, w3l, wdh, wdl, dtb /*unused*/, nullptr, w2h, w2l,
        2048, 2048, 2048, 0);
    cudaEventRecord(evJoin, s2);

    // ---- main branch (stream 0), concurrent with weight GEMM
    // 1. RMSNorm -> split buf0
    rmsnorm_split_kernel<<<NTOK, 256>>>(x, rms_w, ah0, al0);

    // 2. xr = xn @ W_in   [2048,4096], K=1024
    tcgemm_kernel<ACT_NONE, 0, 128><<<dim3(32, 16), 256, SM128>>>(
        ah0, al0, w1h, w1l, xr, nullptr, nullptr, nullptr, 4096, 1024, 4096, 0);

    // 3. conv + silu -> xs fp32 + split buf1
    conv_silu_kernel<<<(NTOK * DINNER / 4) / 256, 256>>>(xr, conv_w, conv_b,
                                                         xs, ah1, al1);

    // ---- join, then fused GEMM2': [dt | B | C] = xs @ [Wc | W_x_BC]
    cudaStreamWaitEvent(0, evJoin, 0);
    tcgemm_kernel<ACT_DTBC, 0, 128><<<dim3(17, 16), 256, SM128>>>(
        ah1, al1, w2h, w2l, dtb, ssm, nullptr, nullptr,
        XW, 2048, DINNER /*ldd: dt*/, XW /*ldr: ssm*/);

    // 6. chunked parallel scan; p2 writes split yz -> buf1
    scan_p1<<<dim3(DINNER / 256, NSEG, BATCH), 256>>>(dtb, xs, ssm, A_log, P, Q);
    scan_combine<<<(BATCH * DSTATE * DINNER) / 256, 256>>>(P, Q, H);
    scan_p2<<<dim3(DINNER / 256, NSEG, BATCH), 256>>>(dtb, xs, ssm, xr, A_log, H,
                                                      ah1, al1);

    // 7. out = x + yz @ W_out   [2048,1024], K=2048  (BM=64 -> 256 CTAs)
    tcgemm_kernel<ACT_RESADD, 0, 64><<<dim3(8, 32), 256, SM64>>>(
        ah1, al1, w4h, w4l, out, x, nullptr, nullptr, 1024, 2048, 1024, 1024);
}